// round 13
// baseline (speedup 1.0000x reference)
#include <cuda_runtime.h>
#include <cuda_fp16.h>
#include <cstdint>

// ---------------------------------------------------------------------------
// Problem constants
// ---------------------------------------------------------------------------
#define BATCH 32
#define CDIM  512
#define NHEAD 16
#define SHIFT 4
#define SEQ   64
#define HEADD 32
#define FFDIM 2048
#define MTOK  131072

// ---------------------------------------------------------------------------
// Scratch
// ---------------------------------------------------------------------------
__device__ __half g_xw  [ (size_t)MTOK * CDIM  ];
__device__ __half g_qkv [ (size_t)MTOK * 3*CDIM];
__device__ __half g_attn[ (size_t)MTOK * CDIM  ];
__device__ __half g_x   [ (size_t)MTOK * CDIM  ];   // residual x, fp16, natural order
__device__ __half g_h   [ (size_t)MTOK * CDIM  ];
__device__ __half g_ff  [ (size_t)MTOK * FFDIM ];
__device__ __half g_wqkvT[3*CDIM * CDIM];
__device__ __half g_woT  [CDIM * CDIM];
__device__ __half g_w1T  [FFDIM * CDIM];
__device__ __half g_w2T  [CDIM * FFDIM];

// ---------------------------------------------------------------------------
// Helpers
// ---------------------------------------------------------------------------
__device__ __forceinline__ void cp16(void* smem, const void* gmem) {
    unsigned s = (unsigned)__cvta_generic_to_shared(smem);
    asm volatile("cp.async.cg.shared.global [%0], [%1], 16;\n" :: "r"(s), "l"(gmem));
}
__device__ __forceinline__ void cp_commit() { asm volatile("cp.async.commit_group;\n"); }
__device__ __forceinline__ void cp_wait1()  { asm volatile("cp.async.wait_group 1;\n"); }
__device__ __forceinline__ void cp_wait0()  { asm volatile("cp.async.wait_group 0;\n"); }

__device__ __forceinline__ void ldm4(uint32_t& r0, uint32_t& r1, uint32_t& r2, uint32_t& r3,
                                     const __half* p) {
    unsigned s = (unsigned)__cvta_generic_to_shared(p);
    asm volatile("ldmatrix.sync.aligned.m8n8.x4.shared.b16 {%0,%1,%2,%3},[%4];\n"
                 : "=r"(r0), "=r"(r1), "=r"(r2), "=r"(r3) : "r"(s));
}
__device__ __forceinline__ void ldm4t(uint32_t& r0, uint32_t& r1, uint32_t& r2, uint32_t& r3,
                                      const __half* p) {
    unsigned s = (unsigned)__cvta_generic_to_shared(p);
    asm volatile("ldmatrix.sync.aligned.m8n8.x4.trans.shared.b16 {%0,%1,%2,%3},[%4];\n"
                 : "=r"(r0), "=r"(r1), "=r"(r2), "=r"(r3) : "r"(s));
}
__device__ __forceinline__ void mma16816(float& c0, float& c1, float& c2, float& c3,
                                         uint32_t a0, uint32_t a1, uint32_t a2, uint32_t a3,
                                         uint32_t b0, uint32_t b1) {
    asm volatile("mma.sync.aligned.m16n8k16.row.col.f32.f16.f16.f32 "
                 "{%0,%1,%2,%3},{%4,%5,%6,%7},{%8,%9},{%0,%1,%2,%3};\n"
                 : "+f"(c0), "+f"(c1), "+f"(c2), "+f"(c3)
                 : "r"(a0), "r"(a1), "r"(a2), "r"(a3), "r"(b0), "r"(b1));
}
__device__ __forceinline__ float gelu_tanh(float x) {
    float x3 = x * x * x;
    return 0.5f * x * (1.0f + tanhf(0.7978845608028654f * (x + 0.044715f * x3)));
}

// ---------------------------------------------------------------------------
// Weight transpose + fp32->fp16 convert: W[K][N] -> Wt[N][K]
// ---------------------------------------------------------------------------
__global__ void k_transpose(const float* __restrict__ W, __half* __restrict__ Wt,
                            int K, int N) {
    int i = blockIdx.x * 256 + threadIdx.x;
    if (i >= K * N) return;
    int n = i / K;
    int k = i - n * K;
    Wt[i] = __float2half(W[(size_t)k * N + n]);
}

// ---------------------------------------------------------------------------
// Kernel 1: LN1 + roll(-4,-4) + window partition
// ---------------------------------------------------------------------------
__global__ __launch_bounds__(128) void k_ln1(const float* __restrict__ hs,
                                             const float* __restrict__ g,
                                             const float* __restrict__ b,
                                             __half* __restrict__ xw) {
    int n    = blockIdx.x;
    int bimg = n >> 12;
    int rem  = n & 4095;
    int wid  = rem >> 6, t = rem & 63;
    int wy = wid >> 3, wx = wid & 7;
    int hr = wy * 8 + (t >> 3), wr = wx * 8 + (t & 7);
    int h0 = (hr + SHIFT) & 63, w0 = (wr + SHIFT) & 63;
    size_t src = ((size_t)(bimg << 12) + (h0 << 6) + w0) * CDIM;

    int tid = threadIdx.x;
    float4 v = ((const float4*)(hs + src))[tid];
    float s  = v.x + v.y + v.z + v.w;
    float s2 = v.x * v.x + v.y * v.y + v.z * v.z + v.w * v.w;
#pragma unroll
    for (int o = 16; o; o >>= 1) {
        s  += __shfl_xor_sync(0xffffffffu, s,  o);
        s2 += __shfl_xor_sync(0xffffffffu, s2, o);
    }
    __shared__ float rs[4], rq[4];
    int warp = tid >> 5, lane = tid & 31;
    if (lane == 0) { rs[warp] = s; rq[warp] = s2; }
    __syncthreads();
    s  = rs[0] + rs[1] + rs[2] + rs[3];
    s2 = rq[0] + rq[1] + rq[2] + rq[3];
    float mean = s * (1.0f / 512.0f);
    float var  = s2 * (1.0f / 512.0f) - mean * mean;
    float rstd = rsqrtf(var + 1e-5f);

    int c = tid * 4;
    float4 gv = ((const float4*)g)[tid];
    float4 bv = ((const float4*)b)[tid];
    __half2* o = (__half2*)(xw + (size_t)n * CDIM + c);
    o[0] = __floats2half2_rn((v.x - mean) * rstd * gv.x + bv.x,
                             (v.y - mean) * rstd * gv.y + bv.y);
    o[1] = __floats2half2_rn((v.z - mean) * rstd * gv.z + bv.z,
                             (v.w - mean) * rstd * gv.w + bv.w);
}

// ---------------------------------------------------------------------------
// HMMA GEMM (R9 mainloop): 128x128 CTA tile, 4 warps (64x64 warp tiles),
// BK=32, 4-stage smem ring + register fragment double-buffer, 2 CTAs/SM.
// EPI: 0 +bias->fp16 | 2 gelu->fp16 | 3 +bias+res(fp16)->fp32
//      4 +bias + hs(fp32) gathered at window-reversed row -> x fp16 scatter
// ---------------------------------------------------------------------------
#define KW    40
#define ROWB  80
#define STGB  (128 * ROWB)
#define NSTG  4
#define GSM_BIAS 0
#define GSM_A    1024
#define GSM_B    (GSM_A + NSTG * STGB)
#define GSM_TOTAL (GSM_B + NSTG * STGB)

__device__ __forceinline__ void g4_load(char* smem, const __half* A, const __half* Bt,
                                        size_t aBase, size_t bBase, int K,
                                        int st, int ko, int tid) {
    char* pa = smem + GSM_A + st * STGB;
    char* pb = smem + GSM_B + st * STGB;
#pragma unroll
    for (int j = 0; j < 4; j++) {
        int c = tid + 128 * j;
        int r = c >> 2, sg = c & 3;
        cp16(pa + r * ROWB + sg * 16, A + aBase + (size_t)r * K + ko + sg * 8);
        cp16(pb + r * ROWB + sg * 16, Bt + bBase + (size_t)r * K + ko + sg * 8);
    }
}

template <int EPI>
__global__ __launch_bounds__(128, 2) void gemm16(const __half* __restrict__ A,
                                                 const __half* __restrict__ Bt,
                                                 const float* __restrict__ bias,
                                                 const __half* __restrict__ res,
                                                 const float* __restrict__ res32,
                                                 void* __restrict__ outp,
                                                 int M, int N, int K) {
    extern __shared__ char smem[];
    int tid = threadIdx.x;
    int bx = blockIdx.x, by = blockIdx.y;
    size_t aBase = (size_t)by * 128 * K;
    size_t bBase = (size_t)bx * 128 * K;

    ((float*)(smem + GSM_BIAS))[tid] = bias[bx * 128 + tid];

    int niter = K >> 5;

#pragma unroll
    for (int st = 0; st < 3; st++) {
        g4_load(smem, A, Bt, aBase, bBase, K, st, st << 5, tid);
        cp_commit();
    }

    int warp = tid >> 5, lane = tid & 31;
    int wm = warp >> 1, wn = warp & 1;          // 2x2 warps; warp tile 64x64

    float acc[4][8][4];
#pragma unroll
    for (int mi = 0; mi < 4; mi++)
#pragma unroll
        for (int ni = 0; ni < 8; ni++)
#pragma unroll
            for (int j = 0; j < 4; j++) acc[mi][ni][j] = 0.0f;

    int aRow = wm * 64 + (lane & 7) + ((lane >> 3) & 1) * 8;
    int aCol = (lane >> 4) * 8;
    int bRow = wn * 64 + (lane & 7) + (lane >> 4) * 8;
    int bCol = ((lane >> 3) & 1) * 8;

    uint32_t fa[2][4][4];
    uint32_t fb[2][8][2];

    cp_wait1();                   // stages 0,1 resident
    __syncthreads();

    // preload stage 0, ks=0 fragments
    {
        const __half* sa = (const __half*)(smem + GSM_A);
        const __half* sb = (const __half*)(smem + GSM_B);
#pragma unroll
        for (int mi = 0; mi < 4; mi++)
            ldm4(fa[0][mi][0], fa[0][mi][1], fa[0][mi][2], fa[0][mi][3],
                 sa + (size_t)(aRow + mi * 16) * KW + aCol);
#pragma unroll
        for (int nj = 0; nj < 4; nj++) {
            uint32_t q0, q1, q2, q3;
            ldm4(q0, q1, q2, q3, sb + (size_t)(bRow + nj * 16) * KW + bCol);
            fb[0][nj * 2][0] = q0; fb[0][nj * 2][1] = q1;
            fb[0][nj * 2 + 1][0] = q2; fb[0][nj * 2 + 1][1] = q3;
        }
    }

    for (int it = 0; it < niter; ++it) {
        int st = it & 3;
        const __half* sa = (const __half*)(smem + GSM_A + st * STGB);
        const __half* sb = (const __half*)(smem + GSM_B + st * STGB);

        // prefetch ks=1 fragments while computing ks=0
#pragma unroll
        for (int mi = 0; mi < 4; mi++)
            ldm4(fa[1][mi][0], fa[1][mi][1], fa[1][mi][2], fa[1][mi][3],
                 sa + (size_t)(aRow + mi * 16) * KW + 16 + aCol);
#pragma unroll
        for (int nj = 0; nj < 4; nj++) {
            uint32_t q0, q1, q2, q3;
            ldm4(q0, q1, q2, q3, sb + (size_t)(bRow + nj * 16) * KW + 16 + bCol);
            fb[1][nj * 2][0] = q0; fb[1][nj * 2][1] = q1;
            fb[1][nj * 2 + 1][0] = q2; fb[1][nj * 2 + 1][1] = q3;
        }
#pragma unroll
        for (int mi = 0; mi < 4; mi++)
#pragma unroll
            for (int ni = 0; ni < 8; ni++)
                mma16816(acc[mi][ni][0], acc[mi][ni][1], acc[mi][ni][2], acc[mi][ni][3],
                         fa[0][mi][0], fa[0][mi][1], fa[0][mi][2], fa[0][mi][3],
                         fb[0][ni][0], fb[0][ni][1]);

        // ring maintenance; stage it+1 guaranteed resident after wait1
        cp_wait1();
        __syncthreads();
        if (it + 3 < niter)
            g4_load(smem, A, Bt, aBase, bBase, K, (it + 3) & 3, (it + 3) << 5, tid);
        cp_commit();

        // prefetch next stage ks=0 fragments while computing ks=1
        if (it + 1 < niter) {
            int sn = (it + 1) & 3;
            const __half* sa2 = (const __half*)(smem + GSM_A + sn * STGB);
            const __half* sb2 = (const __half*)(smem + GSM_B + sn * STGB);
#pragma unroll
            for (int mi = 0; mi < 4; mi++)
                ldm4(fa[0][mi][0], fa[0][mi][1], fa[0][mi][2], fa[0][mi][3],
                     sa2 + (size_t)(aRow + mi * 16) * KW + aCol);
#pragma unroll
            for (int nj = 0; nj < 4; nj++) {
                uint32_t q0, q1, q2, q3;
                ldm4(q0, q1, q2, q3, sb2 + (size_t)(bRow + nj * 16) * KW + bCol);
                fb[0][nj * 2][0] = q0; fb[0][nj * 2][1] = q1;
                fb[0][nj * 2 + 1][0] = q2; fb[0][nj * 2 + 1][1] = q3;
            }
        }
#pragma unroll
        for (int mi = 0; mi < 4; mi++)
#pragma unroll
            for (int ni = 0; ni < 8; ni++)
                mma16816(acc[mi][ni][0], acc[mi][ni][1], acc[mi][ni][2], acc[mi][ni][3],
                         fa[1][mi][0], fa[1][mi][1], fa[1][mi][2], fa[1][mi][3],
                         fb[1][ni][0], fb[1][ni][1]);
    }

    // epilogue
    const float* sbias = (const float*)(smem + GSM_BIAS);
    int gm0 = by * 128 + wm * 64;
    int gn0 = bx * 128 + wn * 64;
    int ln0 = wn * 64;

    if constexpr (EPI == 4) {
        // fused window-reverse + roll(+4,+4) + hs residual -> x (fp16, natural)
#pragma unroll
        for (int mi = 0; mi < 4; mi++) {
#pragma unroll
            for (int hf = 0; hf < 2; hf++) {
                int gr = gm0 + mi * 16 + (lane >> 2) + hf * 8;   // window-order row
                int bimg = gr >> 12;
                int rem  = gr & 4095;
                int wid  = rem >> 6, t = rem & 63;
                int wy = wid >> 3, wx = wid & 7;
                int hr = wy * 8 + (t >> 3), wr = wx * 8 + (t & 7);
                int h0 = (hr + SHIFT) & 63, w0 = (wr + SHIFT) & 63;
                size_t nat = (size_t)(bimg << 12) + (h0 << 6) + w0;
#pragma unroll
                for (int ni = 0; ni < 8; ni++) {
                    int col = gn0 + ni * 8 + (lane & 3) * 2;
                    int lcol = ln0 + ni * 8 + (lane & 3) * 2;
                    float v0 = acc[mi][ni][hf * 2 + 0] + sbias[lcol];
                    float v1 = acc[mi][ni][hf * 2 + 1] + sbias[lcol + 1];
                    float2 hv = *(const float2*)(res32 + nat * CDIM + col);
                    *(__half2*)((__half*)outp + nat * CDIM + col) =
                        __floats2half2_rn(v0 + hv.x, v1 + hv.y);
                }
            }
        }
    } else {
#pragma unroll
        for (int mi = 0; mi < 4; mi++) {
#pragma unroll
            for (int ni = 0; ni < 8; ni++) {
                int row = gm0 + mi * 16 + (lane >> 2);
                int col = gn0 + ni * 8 + (lane & 3) * 2;
                int lcol = ln0 + ni * 8 + (lane & 3) * 2;
                float bv0 = sbias[lcol], bv1 = sbias[lcol + 1];
#pragma unroll
                for (int hf = 0; hf < 2; hf++) {
                    int gr = row + hf * 8;
                    float v0 = acc[mi][ni][hf * 2 + 0] + bv0;
                    float v1 = acc[mi][ni][hf * 2 + 1] + bv1;
                    size_t off = (size_t)gr * N + col;
                    if constexpr (EPI == 0) {
                        *(__half2*)((__half*)outp + off) = __floats2half2_rn(v0, v1);
                    } else if constexpr (EPI == 2) {
                        *(__half2*)((__half*)outp + off) =
                            __floats2half2_rn(gelu_tanh(v0), gelu_tanh(v1));
                    } else {
                        float2 r2 = __half22float2(*(const __half2*)(res + off));
                        v0 += r2.x;
                        v1 += r2.y;
                        *(float2*)((float*)outp + off) = make_float2(v0, v1);
                    }
                }
            }
        }
    }
}

// ---------------------------------------------------------------------------
// Kernel 3: HMMA attention. One WARP per (window, head); block = 4 heads.
// ---------------------------------------------------------------------------
#define ATT_SCALE 0.17677669529663687f
#define AH_HALVES 7680
#define ASM_SID   61440
#define ASM_TOTAL 61696

__global__ __launch_bounds__(128, 2) void k_attn_mma(const __half* __restrict__ qkv,
                                                     __half* __restrict__ attn) {
    extern __shared__ char asmem[];
    int w = blockIdx.x, hg = blockIdx.y;
    int tid = threadIdx.x, wi = tid >> 5, lane = tid & 31;
    int head = hg * 4 + wi;

    __half* sh = (__half*)asmem + wi * AH_HALVES;
    int* sid = (int*)(asmem + ASM_SID);

    const __half* base = qkv + (size_t)w * 64 * 1536 + head * 32;
#pragma unroll
    for (int i = 0; i < 8; i++) {
        int c = lane + 32 * i;
        int r = c >> 2, sg = c & 3;
        const __half* src = base + (size_t)r * 1536 + sg * 8;
        cp16(&sh[r * 40 + sg * 8], src);
        cp16(&sh[2560 + r * 40 + sg * 8], src + 512);
        cp16(&sh[5120 + r * 40 + sg * 8], src + 1024);
    }
    cp_commit();
    if (tid < 64) {
        int wim = w & 63;
        int wy = wim >> 3, wx = wim & 7;
        int hh = wy * 8 + (tid >> 3), ww = wx * 8 + (tid & 7);
        int rh = (hh < 56) ? 0 : ((hh < 60) ? 1 : 2);
        int rw = (ww < 56) ? 0 : ((ww < 60) ? 1 : 2);
        sid[tid] = rh * 3 + rw;
    }
    cp_wait0();
    __syncthreads();

    int aRow = (lane & 7) + ((lane >> 3) & 1) * 8;
    int aCol = (lane >> 4) * 8;
    int bRow = (lane & 7) + (lane >> 4) * 8;
    int bCol = ((lane >> 3) & 1) * 8;

    uint32_t qa[4][2][4];
#pragma unroll
    for (int mi = 0; mi < 4; mi++)
#pragma unroll
        for (int ks = 0; ks < 2; ks++)
            ldm4(qa[mi][ks][0], qa[mi][ks][1], qa[mi][ks][2], qa[mi][ks][3],
                 &sh[(mi * 16 + aRow) * 40 + ks * 16 + aCol]);

    float sc[4][8][4];
#pragma unroll
    for (int mi = 0; mi < 4; mi++)
#pragma unroll
        for (int ni = 0; ni < 8; ni++)
#pragma unroll
            for (int j = 0; j < 4; j++) sc[mi][ni][j] = 0.0f;

    const __half* Ksh = sh + 2560;
#pragma unroll
    for (int nh = 0; nh < 2; nh++) {
        uint32_t kb[4][2][2];
#pragma unroll
        for (int nj2 = 0; nj2 < 2; nj2++)
#pragma unroll
            for (int ks = 0; ks < 2; ks++) {
                uint32_t q0, q1, q2, q3;
                ldm4(q0, q1, q2, q3,
                     &Ksh[(nh * 32 + nj2 * 16 + bRow) * 40 + ks * 16 + bCol]);
                kb[nj2 * 2][ks][0] = q0;     kb[nj2 * 2][ks][1] = q1;
                kb[nj2 * 2 + 1][ks][0] = q2; kb[nj2 * 2 + 1][ks][1] = q3;
            }
#pragma unroll
        for (int mi = 0; mi < 4; mi++)
#pragma unroll
            for (int f = 0; f < 4; f++)
#pragma unroll
                for (int ks = 0; ks < 2; ks++)
                    mma16816(sc[mi][nh * 4 + f][0], sc[mi][nh * 4 + f][1],
                             sc[mi][nh * 4 + f][2], sc[mi][nh * 4 + f][3],
                             qa[mi][ks][0], qa[mi][ks][1], qa[mi][ks][2], qa[mi][ks][3],
                             kb[f][ks][0], kb[f][ks][1]);
    }

    int rsub = lane >> 2;
    int cbase = (lane & 3) * 2;
    int cid[16];
#pragma unroll
    for (int ni = 0; ni < 8; ni++) {
        cid[2 * ni]     = sid[ni * 8 + cbase];
        cid[2 * ni + 1] = sid[ni * 8 + cbase + 1];
    }

    float inv1[4], inv2[4];
    uint32_t pa[4][4][4];
#pragma unroll
    for (int mi = 0; mi < 4; mi++) {
        int rid1 = sid[mi * 16 + rsub];
        int rid2 = sid[mi * 16 + rsub + 8];
#pragma unroll
        for (int ni = 0; ni < 8; ni++) {
            sc[mi][ni][0] = (cid[2 * ni]     == rid1) ? sc[mi][ni][0] * ATT_SCALE : -10000.0f;
            sc[mi][ni][1] = (cid[2 * ni + 1] == rid1) ? sc[mi][ni][1] * ATT_SCALE : -10000.0f;
            sc[mi][ni][2] = (cid[2 * ni]     == rid2) ? sc[mi][ni][2] * ATT_SCALE : -10000.0f;
            sc[mi][ni][3] = (cid[2 * ni + 1] == rid2) ? sc[mi][ni][3] * ATT_SCALE : -10000.0f;
        }
        float m1 = -1e30f, m2 = -1e30f;
#pragma unroll
        for (int ni = 0; ni < 8; ni++) {
            m1 = fmaxf(m1, fmaxf(sc[mi][ni][0], sc[mi][ni][1]));
            m2 = fmaxf(m2, fmaxf(sc[mi][ni][2], sc[mi][ni][3]));
        }
        m1 = fmaxf(m1, __shfl_xor_sync(0xffffffffu, m1, 1));
        m1 = fmaxf(m1, __shfl_xor_sync(0xffffffffu, m1, 2));
        m2 = fmaxf(m2, __shfl_xor_sync(0xffffffffu, m2, 1));
        m2 = fmaxf(m2, __shfl_xor_sync(0xffffffffu, m2, 2));
        float s1 = 0.0f, s2 = 0.0f;
#pragma unroll
        for (int ni = 0; ni < 8; ni++) {
            float e0 = __expf(sc[mi][ni][0] - m1);
            float e1 = __expf(sc[mi][ni][1] - m1);
            float e2 = __expf(sc[mi][ni][2] - m2);
            float e3 = __expf(sc[mi][ni][3] - m2);
            sc[mi][ni][0] = e0; sc[mi][ni][1] = e1;
            sc[mi][ni][2] = e2; sc[mi][ni][3] = e3;
            s1 += e0 + e1; s2 += e2 + e3;
        }
        s1 += __shfl_xor_sync(0xffffffffu, s1, 1);
        s1 += __shfl_xor_sync(0xffffffffu, s1, 2);
        s2 += __shfl_xor_sync(0xffffffffu, s2, 1);
        s2 += __shfl_xor_sync(0xffffffffu, s2, 2);
        inv1[mi] = 1.0f / s1;
        inv2[mi] = 1.0f / s2;
#pragma unroll
        for (int kj = 0; kj < 4; kj++) {
            __half2 h0 = __floats2half2_rn(sc[mi][2 * kj][0], sc[mi][2 * kj][1]);
            __half2 h1 = __floats2half2_rn(sc[mi][2 * kj][2], sc[mi][2 * kj][3]);
            __half2 h2 = __floats2half2_rn(sc[mi][2 * kj + 1][0], sc[mi][2 * kj + 1][1]);
            __half2 h3 = __floats2half2_rn(sc[mi][2 * kj + 1][2], sc[mi][2 * kj + 1][3]);
            pa[mi][kj][0] = *(uint32_t*)&h0;
            pa[mi][kj][1] = *(uint32_t*)&h1;
            pa[mi][kj][2] = *(uint32_t*)&h2;
            pa[mi][kj][3] = *(uint32_t*)&h3;
        }
    }

    float ot[4][4][4];
#pragma unroll
    for (int mi = 0; mi < 4; mi++)
#pragma unroll
        for (int nj = 0; nj < 4; nj++)
#pragma unroll
            for (int j = 0; j < 4; j++) ot[mi][nj][j] = 0.0f;

    const __half* Vsh = sh + 5120;
#pragma unroll
    for (int kj = 0; kj < 4; kj++) {
        uint32_t vb[4][2];
#pragma unroll
        for (int g = 0; g < 2; g++) {
            uint32_t q0, q1, q2, q3;
            ldm4t(q0, q1, q2, q3,
                  &Vsh[(kj * 16 + (lane & 7) + ((lane >> 3) & 1) * 8) * 40 +
                       g * 16 + (lane >> 4) * 8]);
            vb[2 * g][0] = q0;     vb[2 * g][1] = q1;
            vb[2 * g + 1][0] = q2; vb[2 * g + 1][1] = q3;
        }
#pragma unroll
        for (int mi = 0; mi < 4; mi++)
#pragma unroll
            for (int nj = 0; nj < 4; nj++)
                mma16816(ot[mi][nj][0], ot[mi][nj][1], ot[mi][nj][2], ot[mi][nj][3],
                         pa[mi][kj][0], pa[mi][kj][1], pa[mi][kj][2], pa[mi][kj][3],
                         vb[nj][0], vb[nj][1]);
    }

#pragma unroll
    for (int mi = 0; mi < 4; mi++) {
        __half* o1 = attn + (size_t)(w * 64 + mi * 16 + rsub) * 512 + head * 32 + cbase;
        __half* o2 = o1 + (size_t)8 * 512;
#pragma unroll
        for (int nj = 0; nj < 4; nj++) {
            *(__half2*)(o1 + nj * 8) =
                __floats2half2_rn(ot[mi][nj][0] * inv1[mi], ot[mi][nj][1] * inv1[mi]);
            *(__half2*)(o2 + nj * 8) =
                __floats2half2_rn(ot[mi][nj][2] * inv2[mi], ot[mi][nj][3] * inv2[mi]);
        }
    }
}

// ---------------------------------------------------------------------------
// Kernel 5: plain LN2 over x (fp16, natural order) -> h (fp16)
// ---------------------------------------------------------------------------
__global__ __launch_bounds__(128) void k_ln2(const __half* __restrict__ x,
                                             const float* __restrict__ g,
                                             const float* __restrict__ b,
                                             __half* __restrict__ hout) {
    int m = blockIdx.x;
    int tid = threadIdx.x;
    uint2 xv = ((const uint2*)(x + (size_t)m * CDIM))[tid];
    float2 a0 = __half22float2(*(__half2*)&xv.x);
    float2 a1 = __half22float2(*(__half2*)&xv.y);
    float4 v = make_float4(a0.x, a0.y, a1.x, a1.y);

    float s  = v.x + v.y + v.z + v.w;
    float s2 = v.x * v.x + v.y * v.y + v.z * v.z + v.w * v.w;
#pragma unroll
    for (int o = 16; o; o >>= 1) {
        s  += __shfl_xor_sync(0xffffffffu, s,  o);
        s2 += __shfl_xor_sync(0xffffffffu, s2, o);
    }
    __shared__ float rs[4], rq[4];
    int warp = tid >> 5, lane = tid & 31;
    if (lane == 0) { rs[warp] = s; rq[warp] = s2; }
    __syncthreads();
    s  = rs[0] + rs[1] + rs[2] + rs[3];
    s2 = rq[0] + rq[1] + rq[2] + rq[3];
    float mean = s * (1.0f / 512.0f);
    float var  = s2 * (1.0f / 512.0f) - mean * mean;
    float rstd = rsqrtf(var + 1e-5f);

    int c = tid * 4;
    float4 gv = ((const float4*)g)[tid];
    float4 bv = ((const float4*)b)[tid];
    __half2* o = (__half2*)(hout + (size_t)m * CDIM + c);
    o[0] = __floats2half2_rn((v.x - mean) * rstd * gv.x + bv.x,
                             (v.y - mean) * rstd * gv.y + bv.y);
    o[1] = __floats2half2_rn((v.z - mean) * rstd * gv.z + bv.z,
                             (v.w - mean) * rstd * gv.w + bv.w);
}

// ---------------------------------------------------------------------------
// Host launcher (QKV GEMM at launch idx 3 so the profiler captures it)
// ---------------------------------------------------------------------------
extern "C" void kernel_launch(void* const* d_in, const int* in_sizes, int n_in,
                              void* d_out, int out_size) {
    const float* hs   = (const float*)d_in[0];
    const float* Wqkv = (const float*)d_in[1];
    const float* bqkv = (const float*)d_in[2];
    const float* Wo   = (const float*)d_in[3];
    const float* bo   = (const float*)d_in[4];
    const float* ln1g = (const float*)d_in[5];
    const float* ln1b = (const float*)d_in[6];
    const float* ln2g = (const float*)d_in[7];
    const float* ln2b = (const float*)d_in[8];
    const float* W1   = (const float*)d_in[9];
    const float* b1   = (const float*)d_in[10];
    const float* W2   = (const float*)d_in[11];
    const float* b2   = (const float*)d_in[12];

    __half *xw, *qkv, *attn, *xbuf, *hbuf, *ff, *wqkvT, *woT, *w1T, *w2T;
    cudaGetSymbolAddress((void**)&xw,    g_xw);
    cudaGetSymbolAddress((void**)&qkv,   g_qkv);
    cudaGetSymbolAddress((void**)&attn,  g_attn);
    cudaGetSymbolAddress((void**)&xbuf,  g_x);
    cudaGetSymbolAddress((void**)&hbuf,  g_h);
    cudaGetSymbolAddress((void**)&ff,    g_ff);
    cudaGetSymbolAddress((void**)&wqkvT, g_wqkvT);
    cudaGetSymbolAddress((void**)&woT,   g_woT);
    cudaGetSymbolAddress((void**)&w1T,   g_w1T);
    cudaGetSymbolAddress((void**)&w2T,   g_w2T);

    cudaFuncSetAttribute(gemm16<0>, cudaFuncAttributeMaxDynamicSharedMemorySize, GSM_TOTAL);
    cudaFuncSetAttribute(gemm16<2>, cudaFuncAttributeMaxDynamicSharedMemorySize, GSM_TOTAL);
    cudaFuncSetAttribute(gemm16<3>, cudaFuncAttributeMaxDynamicSharedMemorySize, GSM_TOTAL);
    cudaFuncSetAttribute(gemm16<4>, cudaFuncAttributeMaxDynamicSharedMemorySize, GSM_TOTAL);
    cudaFuncSetAttribute(k_attn_mma, cudaFuncAttributeMaxDynamicSharedMemorySize, ASM_TOTAL);

    // 0: Wqkv transpose
    k_transpose<<<(512 * 1536 + 255) / 256, 256>>>(Wqkv, wqkvT, 512, 1536);
    // 1: LN1 + shift + partition
    k_ln1<<<MTOK, 128>>>(hs, ln1g, ln1b, xw);
    // 2: Wo transpose (filler so idx 3 = QKV GEMM)
    k_transpose<<<(512 * 512 + 255) / 256, 256>>>(Wo, woT, 512, 512);
    // 3: QKV GEMM  <-- profiled
    gemm16<0><<<dim3(1536 / 128, MTOK / 128), 128, GSM_TOTAL>>>(
        xw, wqkvT, bqkv, nullptr, nullptr, qkv, MTOK, 1536, 512);
    // 4: attention
    k_attn_mma<<<dim3(2048, 4), 128, ASM_TOTAL>>>(qkv, attn);
    // 5: out projection fused with window-reverse + roll + residual -> x fp16
    gemm16<4><<<dim3(512 / 128, MTOK / 128), 128, GSM_TOTAL>>>(
        attn, woT, bo, nullptr, hs, xbuf, MTOK, 512, 512);
    // 6: W1 transpose
    k_transpose<<<(512 * 2048 + 255) / 256, 256>>>(W1, w1T, 512, 2048);
    // 7: LN2 (plain, x already natural order)
    k_ln2<<<MTOK, 128>>>(xbuf, ln2g, ln2b, hbuf);
    // 8: MLP up + gelu
    gemm16<2><<<dim3(2048 / 128, MTOK / 128), 128, GSM_TOTAL>>>(
        hbuf, w1T, b1, nullptr, nullptr, ff, MTOK, 2048, 512);
    // 9: W2 transpose
    k_transpose<<<(2048 * 512 + 255) / 256, 256>>>(W2, w2T, 2048, 512);
    // 10: MLP down + residual(fp16) -> d_out fp32
    gemm16<3><<<dim3(512 / 128, MTOK / 128), 128, GSM_TOTAL>>>(
        ff, w2T, b2, xbuf, nullptr, d_out, MTOK, 512, 2048);
}

// round 14
// speedup vs baseline: 1.0066x; 1.0066x over previous
#include <cuda_runtime.h>
#include <cuda_fp16.h>
#include <cstdint>

// ---------------------------------------------------------------------------
// Problem constants
// ---------------------------------------------------------------------------
#define BATCH 32
#define CDIM  512
#define NHEAD 16
#define SHIFT 4
#define SEQ   64
#define HEADD 32
#define FFDIM 2048
#define MTOK  131072

// ---------------------------------------------------------------------------
// Scratch
// ---------------------------------------------------------------------------
__device__ __half g_xw  [ (size_t)MTOK * CDIM  ];
__device__ __half g_qkv [ (size_t)MTOK * 3*CDIM];
__device__ __half g_attn[ (size_t)MTOK * CDIM  ];
__device__ __half g_x   [ (size_t)MTOK * CDIM  ];   // residual x, fp16, natural order
__device__ __half g_ff  [ (size_t)MTOK * FFDIM ];
__device__ float  g_stat[ (size_t)MTOK * 2     ];   // per-row {mean, rstd} of x
__device__ float  g_c   [ FFDIM ];                  // c_n  = sum_k g_k W1[k,n]
__device__ float  g_bb  [ FFDIM ];                  // bb_n = sum_k b_k W1[k,n] + b1_n
__device__ __half g_wqkvT[3*CDIM * CDIM];
__device__ __half g_woT  [CDIM * CDIM];
__device__ __half g_w1T  [FFDIM * CDIM];            // rows scaled by ln2_g
__device__ __half g_w2T  [CDIM * FFDIM];

// ---------------------------------------------------------------------------
// Helpers
// ---------------------------------------------------------------------------
__device__ __forceinline__ void cp16(void* smem, const void* gmem) {
    unsigned s = (unsigned)__cvta_generic_to_shared(smem);
    asm volatile("cp.async.cg.shared.global [%0], [%1], 16;\n" :: "r"(s), "l"(gmem));
}
__device__ __forceinline__ void cp_commit() { asm volatile("cp.async.commit_group;\n"); }
__device__ __forceinline__ void cp_wait1()  { asm volatile("cp.async.wait_group 1;\n"); }
__device__ __forceinline__ void cp_wait0()  { asm volatile("cp.async.wait_group 0;\n"); }

__device__ __forceinline__ void ldm4(uint32_t& r0, uint32_t& r1, uint32_t& r2, uint32_t& r3,
                                     const __half* p) {
    unsigned s = (unsigned)__cvta_generic_to_shared(p);
    asm volatile("ldmatrix.sync.aligned.m8n8.x4.shared.b16 {%0,%1,%2,%3},[%4];\n"
                 : "=r"(r0), "=r"(r1), "=r"(r2), "=r"(r3) : "r"(s));
}
__device__ __forceinline__ void ldm4t(uint32_t& r0, uint32_t& r1, uint32_t& r2, uint32_t& r3,
                                      const __half* p) {
    unsigned s = (unsigned)__cvta_generic_to_shared(p);
    asm volatile("ldmatrix.sync.aligned.m8n8.x4.trans.shared.b16 {%0,%1,%2,%3},[%4];\n"
                 : "=r"(r0), "=r"(r1), "=r"(r2), "=r"(r3) : "r"(s));
}
__device__ __forceinline__ void mma16816(float& c0, float& c1, float& c2, float& c3,
                                         uint32_t a0, uint32_t a1, uint32_t a2, uint32_t a3,
                                         uint32_t b0, uint32_t b1) {
    asm volatile("mma.sync.aligned.m16n8k16.row.col.f32.f16.f16.f32 "
                 "{%0,%1,%2,%3},{%4,%5,%6,%7},{%8,%9},{%0,%1,%2,%3};\n"
                 : "+f"(c0), "+f"(c1), "+f"(c2), "+f"(c3)
                 : "r"(a0), "r"(a1), "r"(a2), "r"(a3), "r"(b0), "r"(b1));
}
__device__ __forceinline__ float gelu_tanh(float x) {
    float x3 = x * x * x;
    return 0.5f * x * (1.0f + tanhf(0.7978845608028654f * (x + 0.044715f * x3)));
}

// ---------------------------------------------------------------------------
// Weight transposes
// ---------------------------------------------------------------------------
__global__ void k_transpose(const float* __restrict__ W, __half* __restrict__ Wt,
                            int K, int N) {
    int i = blockIdx.x * 256 + threadIdx.x;
    if (i >= K * N) return;
    int n = i / K;
    int k = i - n * K;
    Wt[i] = __float2half(W[(size_t)k * N + n]);
}
// W1 transpose with per-row (k) scale by ln2_g
__global__ void k_transpose_s(const float* __restrict__ W, const float* __restrict__ g,
                              __half* __restrict__ Wt, int K, int N) {
    int i = blockIdx.x * 256 + threadIdx.x;
    if (i >= K * N) return;
    int n = i / K;
    int k = i - n * K;
    Wt[i] = __float2half(W[(size_t)k * N + n] * g[k]);
}
// c_n = sum_k g_k W1[k,n];  bb_n = sum_k b_k W1[k,n] + b1_n
__global__ void k_vec(const float* __restrict__ W1, const float* __restrict__ g,
                      const float* __restrict__ b, const float* __restrict__ b1,
                      float* __restrict__ cvec, float* __restrict__ bbvec) {
    int n = blockIdx.x * 256 + threadIdx.x;
    if (n >= FFDIM) return;
    float c = 0.0f, d = 0.0f;
    for (int k = 0; k < CDIM; k++) {
        float w = W1[(size_t)k * FFDIM + n];
        c += g[k] * w;
        d += b[k] * w;
    }
    cvec[n]  = c;
    bbvec[n] = d + b1[n];
}

// ---------------------------------------------------------------------------
// Kernel 1: LN1 + roll(-4,-4) + window partition
// ---------------------------------------------------------------------------
__global__ __launch_bounds__(128) void k_ln1(const float* __restrict__ hs,
                                             const float* __restrict__ g,
                                             const float* __restrict__ b,
                                             __half* __restrict__ xw) {
    int n    = blockIdx.x;
    int bimg = n >> 12;
    int rem  = n & 4095;
    int wid  = rem >> 6, t = rem & 63;
    int wy = wid >> 3, wx = wid & 7;
    int hr = wy * 8 + (t >> 3), wr = wx * 8 + (t & 7);
    int h0 = (hr + SHIFT) & 63, w0 = (wr + SHIFT) & 63;
    size_t src = ((size_t)(bimg << 12) + (h0 << 6) + w0) * CDIM;

    int tid = threadIdx.x;
    float4 v = ((const float4*)(hs + src))[tid];
    float s  = v.x + v.y + v.z + v.w;
    float s2 = v.x * v.x + v.y * v.y + v.z * v.z + v.w * v.w;
#pragma unroll
    for (int o = 16; o; o >>= 1) {
        s  += __shfl_xor_sync(0xffffffffu, s,  o);
        s2 += __shfl_xor_sync(0xffffffffu, s2, o);
    }
    __shared__ float rs[4], rq[4];
    int warp = tid >> 5, lane = tid & 31;
    if (lane == 0) { rs[warp] = s; rq[warp] = s2; }
    __syncthreads();
    s  = rs[0] + rs[1] + rs[2] + rs[3];
    s2 = rq[0] + rq[1] + rq[2] + rq[3];
    float mean = s * (1.0f / 512.0f);
    float var  = s2 * (1.0f / 512.0f) - mean * mean;
    float rstd = rsqrtf(var + 1e-5f);

    int c = tid * 4;
    float4 gv = ((const float4*)g)[tid];
    float4 bv = ((const float4*)b)[tid];
    __half2* o = (__half2*)(xw + (size_t)n * CDIM + c);
    o[0] = __floats2half2_rn((v.x - mean) * rstd * gv.x + bv.x,
                             (v.y - mean) * rstd * gv.y + bv.y);
    o[1] = __floats2half2_rn((v.z - mean) * rstd * gv.z + bv.z,
                             (v.w - mean) * rstd * gv.w + bv.w);
}

// ---------------------------------------------------------------------------
// Kernel: per-row mean/rstd of x (fp16) -> g_stat
// ---------------------------------------------------------------------------
__global__ __launch_bounds__(128) void k_stats(const __half* __restrict__ x,
                                               float* __restrict__ stat) {
    int m = blockIdx.x;
    int tid = threadIdx.x;
    uint2 xv = ((const uint2*)(x + (size_t)m * CDIM))[tid];
    float2 a0 = __half22float2(*(__half2*)&xv.x);
    float2 a1 = __half22float2(*(__half2*)&xv.y);
    float s  = a0.x + a0.y + a1.x + a1.y;
    float s2 = a0.x * a0.x + a0.y * a0.y + a1.x * a1.x + a1.y * a1.y;
#pragma unroll
    for (int o = 16; o; o >>= 1) {
        s  += __shfl_xor_sync(0xffffffffu, s,  o);
        s2 += __shfl_xor_sync(0xffffffffu, s2, o);
    }
    __shared__ float rs[4], rq[4];
    int warp = tid >> 5, lane = tid & 31;
    if (lane == 0) { rs[warp] = s; rq[warp] = s2; }
    __syncthreads();
    if (tid == 0) {
        s  = rs[0] + rs[1] + rs[2] + rs[3];
        s2 = rq[0] + rq[1] + rq[2] + rq[3];
        float mean = s * (1.0f / 512.0f);
        float var  = s2 * (1.0f / 512.0f) - mean * mean;
        ((float2*)stat)[m] = make_float2(mean, rsqrtf(var + 1e-5f));
    }
}

// ---------------------------------------------------------------------------
// HMMA GEMM (R9 mainloop): 128x128 CTA tile, 4 warps (64x64 warp tiles),
// BK=32, 4-stage smem ring + register fragment double-buffer, 2 CTAs/SM.
// EPI: 0 +bias->fp16 | 3 +bias+res(fp16)->fp32
//      4 +bias + hs(fp32) gathered at window-reversed row -> x fp16 scatter
//      5 LN2-folded MLP1: gelu(rstd*acc - mean*rstd*c + bb) -> fp16
// ---------------------------------------------------------------------------
#define KW    40
#define ROWB  80
#define STGB  (128 * ROWB)
#define NSTG  4
#define GSM_BIAS 0
#define GSM_A    1024
#define GSM_B    (GSM_A + NSTG * STGB)
#define GSM_TOTAL (GSM_B + NSTG * STGB)

__device__ __forceinline__ void g4_load(char* smem, const __half* A, const __half* Bt,
                                        size_t aBase, size_t bBase, int K,
                                        int st, int ko, int tid) {
    char* pa = smem + GSM_A + st * STGB;
    char* pb = smem + GSM_B + st * STGB;
#pragma unroll
    for (int j = 0; j < 4; j++) {
        int c = tid + 128 * j;
        int r = c >> 2, sg = c & 3;
        cp16(pa + r * ROWB + sg * 16, A + aBase + (size_t)r * K + ko + sg * 8);
        cp16(pb + r * ROWB + sg * 16, Bt + bBase + (size_t)r * K + ko + sg * 8);
    }
}

template <int EPI>
__global__ __launch_bounds__(128, 2) void gemm16(const __half* __restrict__ A,
                                                 const __half* __restrict__ Bt,
                                                 const float* __restrict__ bias,
                                                 const __half* __restrict__ res,
                                                 const float* __restrict__ res32,
                                                 const float* __restrict__ stats,
                                                 const float* __restrict__ cvec,
                                                 void* __restrict__ outp,
                                                 int M, int N, int K) {
    extern __shared__ char smem[];
    int tid = threadIdx.x;
    int bx = blockIdx.x, by = blockIdx.y;
    size_t aBase = (size_t)by * 128 * K;
    size_t bBase = (size_t)bx * 128 * K;

    ((float*)(smem + GSM_BIAS))[tid] = bias[bx * 128 + tid];
    if constexpr (EPI == 5)
        ((float*)(smem + GSM_BIAS))[128 + tid] = cvec[bx * 128 + tid];

    int niter = K >> 5;

#pragma unroll
    for (int st = 0; st < 3; st++) {
        g4_load(smem, A, Bt, aBase, bBase, K, st, st << 5, tid);
        cp_commit();
    }

    int warp = tid >> 5, lane = tid & 31;
    int wm = warp >> 1, wn = warp & 1;          // 2x2 warps; warp tile 64x64

    float acc[4][8][4];
#pragma unroll
    for (int mi = 0; mi < 4; mi++)
#pragma unroll
        for (int ni = 0; ni < 8; ni++)
#pragma unroll
            for (int j = 0; j < 4; j++) acc[mi][ni][j] = 0.0f;

    int aRow = wm * 64 + (lane & 7) + ((lane >> 3) & 1) * 8;
    int aCol = (lane >> 4) * 8;
    int bRow = wn * 64 + (lane & 7) + (lane >> 4) * 8;
    int bCol = ((lane >> 3) & 1) * 8;

    uint32_t fa[2][4][4];
    uint32_t fb[2][8][2];

    cp_wait1();                   // stages 0,1 resident
    __syncthreads();

    // preload stage 0, ks=0 fragments
    {
        const __half* sa = (const __half*)(smem + GSM_A);
        const __half* sb = (const __half*)(smem + GSM_B);
#pragma unroll
        for (int mi = 0; mi < 4; mi++)
            ldm4(fa[0][mi][0], fa[0][mi][1], fa[0][mi][2], fa[0][mi][3],
                 sa + (size_t)(aRow + mi * 16) * KW + aCol);
#pragma unroll
        for (int nj = 0; nj < 4; nj++) {
            uint32_t q0, q1, q2, q3;
            ldm4(q0, q1, q2, q3, sb + (size_t)(bRow + nj * 16) * KW + bCol);
            fb[0][nj * 2][0] = q0; fb[0][nj * 2][1] = q1;
            fb[0][nj * 2 + 1][0] = q2; fb[0][nj * 2 + 1][1] = q3;
        }
    }

    for (int it = 0; it < niter; ++it) {
        int st = it & 3;
        const __half* sa = (const __half*)(smem + GSM_A + st * STGB);
        const __half* sb = (const __half*)(smem + GSM_B + st * STGB);

        // prefetch ks=1 fragments while computing ks=0
#pragma unroll
        for (int mi = 0; mi < 4; mi++)
            ldm4(fa[1][mi][0], fa[1][mi][1], fa[1][mi][2], fa[1][mi][3],
                 sa + (size_t)(aRow + mi * 16) * KW + 16 + aCol);
#pragma unroll
        for (int nj = 0; nj < 4; nj++) {
            uint32_t q0, q1, q2, q3;
            ldm4(q0, q1, q2, q3, sb + (size_t)(bRow + nj * 16) * KW + 16 + bCol);
            fb[1][nj * 2][0] = q0; fb[1][nj * 2][1] = q1;
            fb[1][nj * 2 + 1][0] = q2; fb[1][nj * 2 + 1][1] = q3;
        }
#pragma unroll
        for (int mi = 0; mi < 4; mi++)
#pragma unroll
            for (int ni = 0; ni < 8; ni++)
                mma16816(acc[mi][ni][0], acc[mi][ni][1], acc[mi][ni][2], acc[mi][ni][3],
                         fa[0][mi][0], fa[0][mi][1], fa[0][mi][2], fa[0][mi][3],
                         fb[0][ni][0], fb[0][ni][1]);

        cp_wait1();
        __syncthreads();
        if (it + 3 < niter)
            g4_load(smem, A, Bt, aBase, bBase, K, (it + 3) & 3, (it + 3) << 5, tid);
        cp_commit();

        if (it + 1 < niter) {
            int sn = (it + 1) & 3;
            const __half* sa2 = (const __half*)(smem + GSM_A + sn * STGB);
            const __half* sb2 = (const __half*)(smem + GSM_B + sn * STGB);
#pragma unroll
            for (int mi = 0; mi < 4; mi++)
                ldm4(fa[0][mi][0], fa[0][mi][1], fa[0][mi][2], fa[0][mi][3],
                     sa2 + (size_t)(aRow + mi * 16) * KW + aCol);
#pragma unroll
            for (int nj = 0; nj < 4; nj++) {
                uint32_t q0, q1, q2, q3;
                ldm4(q0, q1, q2, q3, sb2 + (size_t)(bRow + nj * 16) * KW + bCol);
                fb[0][nj * 2][0] = q0; fb[0][nj * 2][1] = q1;
                fb[0][nj * 2 + 1][0] = q2; fb[0][nj * 2 + 1][1] = q3;
            }
        }
#pragma unroll
        for (int mi = 0; mi < 4; mi++)
#pragma unroll
            for (int ni = 0; ni < 8; ni++)
                mma16816(acc[mi][ni][0], acc[mi][ni][1], acc[mi][ni][2], acc[mi][ni][3],
                         fa[1][mi][0], fa[1][mi][1], fa[1][mi][2], fa[1][mi][3],
                         fb[1][ni][0], fb[1][ni][1]);
    }

    // epilogue
    const float* sbias = (const float*)(smem + GSM_BIAS);
    int gm0 = by * 128 + wm * 64;
    int gn0 = bx * 128 + wn * 64;
    int ln0 = wn * 64;

    if constexpr (EPI == 4) {
        // fused window-reverse + roll(+4,+4) + hs residual -> x (fp16, natural)
#pragma unroll
        for (int mi = 0; mi < 4; mi++) {
#pragma unroll
            for (int hf = 0; hf < 2; hf++) {
                int gr = gm0 + mi * 16 + (lane >> 2) + hf * 8;
                int bimg = gr >> 12;
                int rem  = gr & 4095;
                int wid  = rem >> 6, t = rem & 63;
                int wy = wid >> 3, wx = wid & 7;
                int hr = wy * 8 + (t >> 3), wr = wx * 8 + (t & 7);
                int h0 = (hr + SHIFT) & 63, w0 = (wr + SHIFT) & 63;
                size_t nat = (size_t)(bimg << 12) + (h0 << 6) + w0;
#pragma unroll
                for (int ni = 0; ni < 8; ni++) {
                    int col = gn0 + ni * 8 + (lane & 3) * 2;
                    int lcol = ln0 + ni * 8 + (lane & 3) * 2;
                    float v0 = acc[mi][ni][hf * 2 + 0] + sbias[lcol];
                    float v1 = acc[mi][ni][hf * 2 + 1] + sbias[lcol + 1];
                    float2 hv = *(const float2*)(res32 + nat * CDIM + col);
                    *(__half2*)((__half*)outp + nat * CDIM + col) =
                        __floats2half2_rn(v0 + hv.x, v1 + hv.y);
                }
            }
        }
    } else if constexpr (EPI == 5) {
        // LN2-folded MLP1: gelu(rstd*acc + (-mean*rstd)*c + bb)
        const float* scv = sbias + 128;
#pragma unroll
        for (int mi = 0; mi < 4; mi++) {
#pragma unroll
            for (int hf = 0; hf < 2; hf++) {
                int gr = gm0 + mi * 16 + (lane >> 2) + hf * 8;
                float2 st2 = ((const float2*)stats)[gr];
                float rstd = st2.y;
                float mr = -st2.x * st2.y;
#pragma unroll
                for (int ni = 0; ni < 8; ni++) {
                    int col = gn0 + ni * 8 + (lane & 3) * 2;
                    int lcol = ln0 + ni * 8 + (lane & 3) * 2;
                    float v0 = fmaf(acc[mi][ni][hf * 2 + 0], rstd,
                                    fmaf(mr, scv[lcol], sbias[lcol]));
                    float v1 = fmaf(acc[mi][ni][hf * 2 + 1], rstd,
                                    fmaf(mr, scv[lcol + 1], sbias[lcol + 1]));
                    *(__half2*)((__half*)outp + (size_t)gr * N + col) =
                        __floats2half2_rn(gelu_tanh(v0), gelu_tanh(v1));
                }
            }
        }
    } else {
#pragma unroll
        for (int mi = 0; mi < 4; mi++) {
#pragma unroll
            for (int ni = 0; ni < 8; ni++) {
                int row = gm0 + mi * 16 + (lane >> 2);
                int col = gn0 + ni * 8 + (lane & 3) * 2;
                int lcol = ln0 + ni * 8 + (lane & 3) * 2;
                float bv0 = sbias[lcol], bv1 = sbias[lcol + 1];
#pragma unroll
                for (int hf = 0; hf < 2; hf++) {
                    int gr = row + hf * 8;
                    float v0 = acc[mi][ni][hf * 2 + 0] + bv0;
                    float v1 = acc[mi][ni][hf * 2 + 1] + bv1;
                    size_t off = (size_t)gr * N + col;
                    if constexpr (EPI == 0) {
                        *(__half2*)((__half*)outp + off) = __floats2half2_rn(v0, v1);
                    } else {
                        float2 r2 = __half22float2(*(const __half2*)(res + off));
                        v0 += r2.x;
                        v1 += r2.y;
                        *(float2*)((float*)outp + off) = make_float2(v0, v1);
                    }
                }
            }
        }
    }
}

// ---------------------------------------------------------------------------
// Kernel 3: HMMA attention. One WARP per (window, head); block = 4 heads.
// ---------------------------------------------------------------------------
#define ATT_SCALE 0.17677669529663687f
#define AH_HALVES 7680
#define ASM_SID   61440
#define ASM_TOTAL 61696

__global__ __launch_bounds__(128, 2) void k_attn_mma(const __half* __restrict__ qkv,
                                                     __half* __restrict__ attn) {
    extern __shared__ char asmem[];
    int w = blockIdx.x, hg = blockIdx.y;
    int tid = threadIdx.x, wi = tid >> 5, lane = tid & 31;
    int head = hg * 4 + wi;

    __half* sh = (__half*)asmem + wi * AH_HALVES;
    int* sid = (int*)(asmem + ASM_SID);

    const __half* base = qkv + (size_t)w * 64 * 1536 + head * 32;
#pragma unroll
    for (int i = 0; i < 8; i++) {
        int c = lane + 32 * i;
        int r = c >> 2, sg = c & 3;
        const __half* src = base + (size_t)r * 1536 + sg * 8;
        cp16(&sh[r * 40 + sg * 8], src);
        cp16(&sh[2560 + r * 40 + sg * 8], src + 512);
        cp16(&sh[5120 + r * 40 + sg * 8], src + 1024);
    }
    cp_commit();
    if (tid < 64) {
        int wim = w & 63;
        int wy = wim >> 3, wx = wim & 7;
        int hh = wy * 8 + (tid >> 3), ww = wx * 8 + (tid & 7);
        int rh = (hh < 56) ? 0 : ((hh < 60) ? 1 : 2);
        int rw = (ww < 56) ? 0 : ((ww < 60) ? 1 : 2);
        sid[tid] = rh * 3 + rw;
    }
    cp_wait0();
    __syncthreads();

    int aRow = (lane & 7) + ((lane >> 3) & 1) * 8;
    int aCol = (lane >> 4) * 8;
    int bRow = (lane & 7) + (lane >> 4) * 8;
    int bCol = ((lane >> 3) & 1) * 8;

    uint32_t qa[4][2][4];
#pragma unroll
    for (int mi = 0; mi < 4; mi++)
#pragma unroll
        for (int ks = 0; ks < 2; ks++)
            ldm4(qa[mi][ks][0], qa[mi][ks][1], qa[mi][ks][2], qa[mi][ks][3],
                 &sh[(mi * 16 + aRow) * 40 + ks * 16 + aCol]);

    float sc[4][8][4];
#pragma unroll
    for (int mi = 0; mi < 4; mi++)
#pragma unroll
        for (int ni = 0; ni < 8; ni++)
#pragma unroll
            for (int j = 0; j < 4; j++) sc[mi][ni][j] = 0.0f;

    const __half* Ksh = sh + 2560;
#pragma unroll
    for (int nh = 0; nh < 2; nh++) {
        uint32_t kb[4][2][2];
#pragma unroll
        for (int nj2 = 0; nj2 < 2; nj2++)
#pragma unroll
            for (int ks = 0; ks < 2; ks++) {
                uint32_t q0, q1, q2, q3;
                ldm4(q0, q1, q2, q3,
                     &Ksh[(nh * 32 + nj2 * 16 + bRow) * 40 + ks * 16 + bCol]);
                kb[nj2 * 2][ks][0] = q0;     kb[nj2 * 2][ks][1] = q1;
                kb[nj2 * 2 + 1][ks][0] = q2; kb[nj2 * 2 + 1][ks][1] = q3;
            }
#pragma unroll
        for (int mi = 0; mi < 4; mi++)
#pragma unroll
            for (int f = 0; f < 4; f++)
#pragma unroll
                for (int ks = 0; ks < 2; ks++)
                    mma16816(sc[mi][nh * 4 + f][0], sc[mi][nh * 4 + f][1],
                             sc[mi][nh * 4 + f][2], sc[mi][nh * 4 + f][3],
                             qa[mi][ks][0], qa[mi][ks][1], qa[mi][ks][2], qa[mi][ks][3],
                             kb[f][ks][0], kb[f][ks][1]);
    }

    int rsub = lane >> 2;
    int cbase = (lane & 3) * 2;
    int cid[16];
#pragma unroll
    for (int ni = 0; ni < 8; ni++) {
        cid[2 * ni]     = sid[ni * 8 + cbase];
        cid[2 * ni + 1] = sid[ni * 8 + cbase + 1];
    }

    float inv1[4], inv2[4];
    uint32_t pa[4][4][4];
#pragma unroll
    for (int mi = 0; mi < 4; mi++) {
        int rid1 = sid[mi * 16 + rsub];
        int rid2 = sid[mi * 16 + rsub + 8];
#pragma unroll
        for (int ni = 0; ni < 8; ni++) {
            sc[mi][ni][0] = (cid[2 * ni]     == rid1) ? sc[mi][ni][0] * ATT_SCALE : -10000.0f;
            sc[mi][ni][1] = (cid[2 * ni + 1] == rid1) ? sc[mi][ni][1] * ATT_SCALE : -10000.0f;
            sc[mi][ni][2] = (cid[2 * ni]     == rid2) ? sc[mi][ni][2] * ATT_SCALE : -10000.0f;
            sc[mi][ni][3] = (cid[2 * ni + 1] == rid2) ? sc[mi][ni][3] * ATT_SCALE : -10000.0f;
        }
        float m1 = -1e30f, m2 = -1e30f;
#pragma unroll
        for (int ni = 0; ni < 8; ni++) {
            m1 = fmaxf(m1, fmaxf(sc[mi][ni][0], sc[mi][ni][1]));
            m2 = fmaxf(m2, fmaxf(sc[mi][ni][2], sc[mi][ni][3]));
        }
        m1 = fmaxf(m1, __shfl_xor_sync(0xffffffffu, m1, 1));
        m1 = fmaxf(m1, __shfl_xor_sync(0xffffffffu, m1, 2));
        m2 = fmaxf(m2, __shfl_xor_sync(0xffffffffu, m2, 1));
        m2 = fmaxf(m2, __shfl_xor_sync(0xffffffffu, m2, 2));
        float s1 = 0.0f, s2 = 0.0f;
#pragma unroll
        for (int ni = 0; ni < 8; ni++) {
            float e0 = __expf(sc[mi][ni][0] - m1);
            float e1 = __expf(sc[mi][ni][1] - m1);
            float e2 = __expf(sc[mi][ni][2] - m2);
            float e3 = __expf(sc[mi][ni][3] - m2);
            sc[mi][ni][0] = e0; sc[mi][ni][1] = e1;
            sc[mi][ni][2] = e2; sc[mi][ni][3] = e3;
            s1 += e0 + e1; s2 += e2 + e3;
        }
        s1 += __shfl_xor_sync(0xffffffffu, s1, 1);
        s1 += __shfl_xor_sync(0xffffffffu, s1, 2);
        s2 += __shfl_xor_sync(0xffffffffu, s2, 1);
        s2 += __shfl_xor_sync(0xffffffffu, s2, 2);
        inv1[mi] = 1.0f / s1;
        inv2[mi] = 1.0f / s2;
#pragma unroll
        for (int kj = 0; kj < 4; kj++) {
            __half2 h0 = __floats2half2_rn(sc[mi][2 * kj][0], sc[mi][2 * kj][1]);
            __half2 h1 = __floats2half2_rn(sc[mi][2 * kj][2], sc[mi][2 * kj][3]);
            __half2 h2 = __floats2half2_rn(sc[mi][2 * kj + 1][0], sc[mi][2 * kj + 1][1]);
            __half2 h3 = __floats2half2_rn(sc[mi][2 * kj + 1][2], sc[mi][2 * kj + 1][3]);
            pa[mi][kj][0] = *(uint32_t*)&h0;
            pa[mi][kj][1] = *(uint32_t*)&h1;
            pa[mi][kj][2] = *(uint32_t*)&h2;
            pa[mi][kj][3] = *(uint32_t*)&h3;
        }
    }

    float ot[4][4][4];
#pragma unroll
    for (int mi = 0; mi < 4; mi++)
#pragma unroll
        for (int nj = 0; nj < 4; nj++)
#pragma unroll
            for (int j = 0; j < 4; j++) ot[mi][nj][j] = 0.0f;

    const __half* Vsh = sh + 5120;
#pragma unroll
    for (int kj = 0; kj < 4; kj++) {
        uint32_t vb[4][2];
#pragma unroll
        for (int g = 0; g < 2; g++) {
            uint32_t q0, q1, q2, q3;
            ldm4t(q0, q1, q2, q3,
                  &Vsh[(kj * 16 + (lane & 7) + ((lane >> 3) & 1) * 8) * 40 +
                       g * 16 + (lane >> 4) * 8]);
            vb[2 * g][0] = q0;     vb[2 * g][1] = q1;
            vb[2 * g + 1][0] = q2; vb[2 * g + 1][1] = q3;
        }
#pragma unroll
        for (int mi = 0; mi < 4; mi++)
#pragma unroll
            for (int nj = 0; nj < 4; nj++)
                mma16816(ot[mi][nj][0], ot[mi][nj][1], ot[mi][nj][2], ot[mi][nj][3],
                         pa[mi][kj][0], pa[mi][kj][1], pa[mi][kj][2], pa[mi][kj][3],
                         vb[nj][0], vb[nj][1]);
    }

#pragma unroll
    for (int mi = 0; mi < 4; mi++) {
        __half* o1 = attn + (size_t)(w * 64 + mi * 16 + rsub) * 512 + head * 32 + cbase;
        __half* o2 = o1 + (size_t)8 * 512;
#pragma unroll
        for (int nj = 0; nj < 4; nj++) {
            *(__half2*)(o1 + nj * 8) =
                __floats2half2_rn(ot[mi][nj][0] * inv1[mi], ot[mi][nj][1] * inv1[mi]);
            *(__half2*)(o2 + nj * 8) =
                __floats2half2_rn(ot[mi][nj][2] * inv2[mi], ot[mi][nj][3] * inv2[mi]);
        }
    }
}

// ---------------------------------------------------------------------------
// Host launcher (QKV GEMM at launch idx 3 so the profiler captures it)
// ---------------------------------------------------------------------------
extern "C" void kernel_launch(void* const* d_in, const int* in_sizes, int n_in,
                              void* d_out, int out_size) {
    const float* hs   = (const float*)d_in[0];
    const float* Wqkv = (const float*)d_in[1];
    const float* bqkv = (const float*)d_in[2];
    const float* Wo   = (const float*)d_in[3];
    const float* bo   = (const float*)d_in[4];
    const float* ln1g = (const float*)d_in[5];
    const float* ln1b = (const float*)d_in[6];
    const float* ln2g = (const float*)d_in[7];
    const float* ln2b = (const float*)d_in[8];
    const float* W1   = (const float*)d_in[9];
    const float* b1   = (const float*)d_in[10];
    const float* W2   = (const float*)d_in[11];
    const float* b2   = (const float*)d_in[12];

    __half *xw, *qkv, *attn, *xbuf, *ff, *wqkvT, *woT, *w1T, *w2T;
    float *stat, *cv, *bb;
    cudaGetSymbolAddress((void**)&xw,    g_xw);
    cudaGetSymbolAddress((void**)&qkv,   g_qkv);
    cudaGetSymbolAddress((void**)&attn,  g_attn);
    cudaGetSymbolAddress((void**)&xbuf,  g_x);
    cudaGetSymbolAddress((void**)&ff,    g_ff);
    cudaGetSymbolAddress((void**)&stat,  g_stat);
    cudaGetSymbolAddress((void**)&cv,    g_c);
    cudaGetSymbolAddress((void**)&bb,    g_bb);
    cudaGetSymbolAddress((void**)&wqkvT, g_wqkvT);
    cudaGetSymbolAddress((void**)&woT,   g_woT);
    cudaGetSymbolAddress((void**)&w1T,   g_w1T);
    cudaGetSymbolAddress((void**)&w2T,   g_w2T);

    cudaFuncSetAttribute(gemm16<0>, cudaFuncAttributeMaxDynamicSharedMemorySize, GSM_TOTAL);
    cudaFuncSetAttribute(gemm16<3>, cudaFuncAttributeMaxDynamicSharedMemorySize, GSM_TOTAL);
    cudaFuncSetAttribute(gemm16<4>, cudaFuncAttributeMaxDynamicSharedMemorySize, GSM_TOTAL);
    cudaFuncSetAttribute(gemm16<5>, cudaFuncAttributeMaxDynamicSharedMemorySize, GSM_TOTAL);
    cudaFuncSetAttribute(k_attn_mma, cudaFuncAttributeMaxDynamicSharedMemorySize, ASM_TOTAL);

    // 0: Wqkv transpose
    k_transpose<<<(512 * 1536 + 255) / 256, 256>>>(Wqkv, wqkvT, 512, 1536);
    // 1: LN1 + shift + partition
    k_ln1<<<MTOK, 128>>>(hs, ln1g, ln1b, xw);
    // 2: Wo transpose (filler so idx 3 = QKV GEMM)
    k_transpose<<<(512 * 512 + 255) / 256, 256>>>(Wo, woT, 512, 512);
    // 3: QKV GEMM  <-- profiled
    gemm16<0><<<dim3(1536 / 128, MTOK / 128), 128, GSM_TOTAL>>>(
        xw, wqkvT, bqkv, nullptr, nullptr, nullptr, nullptr, qkv, MTOK, 1536, 512);
    // 4: attention
    k_attn_mma<<<dim3(2048, 4), 128, ASM_TOTAL>>>(qkv, attn);
    // 5: out projection fused with window-reverse + roll + residual -> x fp16
    gemm16<4><<<dim3(512 / 128, MTOK / 128), 128, GSM_TOTAL>>>(
        attn, woT, bo, nullptr, hs, nullptr, nullptr, xbuf, MTOK, 512, 512);
    // 6: W1 transpose (rows scaled by ln2_g)
    k_transpose_s<<<(512 * 2048 + 255) / 256, 256>>>(W1, ln2g, w1T, 512, 2048);
    // 7: c / bb vectors
    k_vec<<<FFDIM / 256, 256>>>(W1, ln2g, ln2b, b1, cv, bb);
    // 8: per-row stats of x
    k_stats<<<MTOK, 128>>>(xbuf, stat);
    // 9: MLP1 with LN2 folded: gelu(rstd*x.W1' - mean*rstd*c + bb) -> ff
    gemm16<5><<<dim3(2048 / 128, MTOK / 128), 128, GSM_TOTAL>>>(
        xbuf, w1T, bb, nullptr, nullptr, stat, cv, ff, MTOK, 2048, 512);
    // 10: W2 transpose
    k_transpose<<<(2048 * 512 + 255) / 256, 256>>>(W2, w2T, 2048, 512);
    // 11: MLP2 + residual(fp16) -> d_out fp32
    gemm16<3><<<dim3(512 / 128, MTOK / 128), 128, GSM_TOTAL>>>(
        ff, w2T, b2, xbuf, nullptr, nullptr, nullptr, d_out, MTOK, 512, 2048);
}

// round 15
// speedup vs baseline: 1.0315x; 1.0248x over previous
#include <cuda_runtime.h>
#include <cuda_fp16.h>
#include <cstdint>

// ---------------------------------------------------------------------------
// Problem constants
// ---------------------------------------------------------------------------
#define BATCH 32
#define CDIM  512
#define NHEAD 16
#define SHIFT 4
#define SEQ   64
#define HEADD 32
#define FFDIM 2048
#define MTOK  131072

// ---------------------------------------------------------------------------
// Scratch
// ---------------------------------------------------------------------------
__device__ __half g_xw  [ (size_t)MTOK * CDIM  ];
__device__ __half g_qkv [ (size_t)MTOK * 3*CDIM];
__device__ __half g_attn[ (size_t)MTOK * CDIM  ];
__device__ __half g_x   [ (size_t)MTOK * CDIM  ];   // residual x, fp16, natural order
__device__ __half g_ff  [ (size_t)MTOK * FFDIM ];
__device__ float2 g_part[ 4 * (size_t)MTOK     ];   // per-(row, bx) partial {sum, sumsq}
__device__ float  g_stat[ (size_t)MTOK * 2     ];   // per-row {mean, rstd} of x
__device__ float  g_c   [ FFDIM ];
__device__ float  g_bb  [ FFDIM ];
__device__ __half g_wqkvT[3*CDIM * CDIM];
__device__ __half g_woT  [CDIM * CDIM];
__device__ __half g_w1T  [FFDIM * CDIM];            // rows scaled by ln2_g
__device__ __half g_w2T  [CDIM * FFDIM];

// ---------------------------------------------------------------------------
// Helpers
// ---------------------------------------------------------------------------
__device__ __forceinline__ void cp16(void* smem, const void* gmem) {
    unsigned s = (unsigned)__cvta_generic_to_shared(smem);
    asm volatile("cp.async.cg.shared.global [%0], [%1], 16;\n" :: "r"(s), "l"(gmem));
}
__device__ __forceinline__ void cp_commit() { asm volatile("cp.async.commit_group;\n"); }
__device__ __forceinline__ void cp_wait1()  { asm volatile("cp.async.wait_group 1;\n"); }
__device__ __forceinline__ void cp_wait0()  { asm volatile("cp.async.wait_group 0;\n"); }

__device__ __forceinline__ void ldm4(uint32_t& r0, uint32_t& r1, uint32_t& r2, uint32_t& r3,
                                     const __half* p) {
    unsigned s = (unsigned)__cvta_generic_to_shared(p);
    asm volatile("ldmatrix.sync.aligned.m8n8.x4.shared.b16 {%0,%1,%2,%3},[%4];\n"
                 : "=r"(r0), "=r"(r1), "=r"(r2), "=r"(r3) : "r"(s));
}
__device__ __forceinline__ void ldm4t(uint32_t& r0, uint32_t& r1, uint32_t& r2, uint32_t& r3,
                                      const __half* p) {
    unsigned s = (unsigned)__cvta_generic_to_shared(p);
    asm volatile("ldmatrix.sync.aligned.m8n8.x4.trans.shared.b16 {%0,%1,%2,%3},[%4];\n"
                 : "=r"(r0), "=r"(r1), "=r"(r2), "=r"(r3) : "r"(s));
}
__device__ __forceinline__ void mma16816(float& c0, float& c1, float& c2, float& c3,
                                         uint32_t a0, uint32_t a1, uint32_t a2, uint32_t a3,
                                         uint32_t b0, uint32_t b1) {
    asm volatile("mma.sync.aligned.m16n8k16.row.col.f32.f16.f16.f32 "
                 "{%0,%1,%2,%3},{%4,%5,%6,%7},{%8,%9},{%0,%1,%2,%3};\n"
                 : "+f"(c0), "+f"(c1), "+f"(c2), "+f"(c3)
                 : "r"(a0), "r"(a1), "r"(a2), "r"(a3), "r"(b0), "r"(b1));
}
__device__ __forceinline__ float gelu_tanh(float x) {
    float x3 = x * x * x;
    return 0.5f * x * (1.0f + tanhf(0.7978845608028654f * (x + 0.044715f * x3)));
}

// ---------------------------------------------------------------------------
// Weight transposes
// ---------------------------------------------------------------------------
__global__ void k_transpose(const float* __restrict__ W, __half* __restrict__ Wt,
                            int K, int N) {
    int i = blockIdx.x * 256 + threadIdx.x;
    if (i >= K * N) return;
    int n = i / K;
    int k = i - n * K;
    Wt[i] = __float2half(W[(size_t)k * N + n]);
}
__global__ void k_transpose_s(const float* __restrict__ W, const float* __restrict__ g,
                              __half* __restrict__ Wt, int K, int N) {
    int i = blockIdx.x * 256 + threadIdx.x;
    if (i >= K * N) return;
    int n = i / K;
    int k = i - n * K;
    Wt[i] = __float2half(W[(size_t)k * N + n] * g[k]);
}
__global__ void k_vec(const float* __restrict__ W1, const float* __restrict__ g,
                      const float* __restrict__ b, const float* __restrict__ b1,
                      float* __restrict__ cvec, float* __restrict__ bbvec) {
    int n = blockIdx.x * 256 + threadIdx.x;
    if (n >= FFDIM) return;
    float c = 0.0f, d = 0.0f;
    for (int k = 0; k < CDIM; k++) {
        float w = W1[(size_t)k * FFDIM + n];
        c += g[k] * w;
        d += b[k] * w;
    }
    cvec[n]  = c;
    bbvec[n] = d + b1[n];
}

// ---------------------------------------------------------------------------
// Kernel 1: LN1 + roll(-4,-4) + window partition
// ---------------------------------------------------------------------------
__global__ __launch_bounds__(128) void k_ln1(const float* __restrict__ hs,
                                             const float* __restrict__ g,
                                             const float* __restrict__ b,
                                             __half* __restrict__ xw) {
    int n    = blockIdx.x;
    int bimg = n >> 12;
    int rem  = n & 4095;
    int wid  = rem >> 6, t = rem & 63;
    int wy = wid >> 3, wx = wid & 7;
    int hr = wy * 8 + (t >> 3), wr = wx * 8 + (t & 7);
    int h0 = (hr + SHIFT) & 63, w0 = (wr + SHIFT) & 63;
    size_t src = ((size_t)(bimg << 12) + (h0 << 6) + w0) * CDIM;

    int tid = threadIdx.x;
    float4 v = ((const float4*)(hs + src))[tid];
    float s  = v.x + v.y + v.z + v.w;
    float s2 = v.x * v.x + v.y * v.y + v.z * v.z + v.w * v.w;
#pragma unroll
    for (int o = 16; o; o >>= 1) {
        s  += __shfl_xor_sync(0xffffffffu, s,  o);
        s2 += __shfl_xor_sync(0xffffffffu, s2, o);
    }
    __shared__ float rs[4], rq[4];
    int warp = tid >> 5, lane = tid & 31;
    if (lane == 0) { rs[warp] = s; rq[warp] = s2; }
    __syncthreads();
    s  = rs[0] + rs[1] + rs[2] + rs[3];
    s2 = rq[0] + rq[1] + rq[2] + rq[3];
    float mean = s * (1.0f / 512.0f);
    float var  = s2 * (1.0f / 512.0f) - mean * mean;
    float rstd = rsqrtf(var + 1e-5f);

    int c = tid * 4;
    float4 gv = ((const float4*)g)[tid];
    float4 bv = ((const float4*)b)[tid];
    __half2* o = (__half2*)(xw + (size_t)n * CDIM + c);
    o[0] = __floats2half2_rn((v.x - mean) * rstd * gv.x + bv.x,
                             (v.y - mean) * rstd * gv.y + bv.y);
    o[1] = __floats2half2_rn((v.z - mean) * rstd * gv.z + bv.z,
                             (v.w - mean) * rstd * gv.w + bv.w);
}

// ---------------------------------------------------------------------------
// Finalize per-row stats from 4 partial (sum, sumsq) pairs
// ---------------------------------------------------------------------------
__global__ void k_stats_fin(const float2* __restrict__ part,
                            float2* __restrict__ stat) {
    int m = blockIdx.x * 256 + threadIdx.x;
    if (m >= MTOK) return;
    float s = 0.0f, s2 = 0.0f;
#pragma unroll
    for (int j = 0; j < 4; j++) {
        float2 p = part[(size_t)j * MTOK + m];
        s += p.x; s2 += p.y;
    }
    float mean = s * (1.0f / 512.0f);
    float var  = s2 * (1.0f / 512.0f) - mean * mean;
    stat[m] = make_float2(mean, rsqrtf(var + 1e-5f));
}

// ---------------------------------------------------------------------------
// HMMA GEMM (R9 mainloop): 128x128 CTA tile, 4 warps (64x64 warp tiles),
// BK=32, 4-stage smem ring + register fragment double-buffer, 2 CTAs/SM.
// EPI: 0 +bias->fp16 | 3 +bias+res(fp16)->fp32
//      4 +bias + hs gather (window-reversed) -> x fp16 scatter + stat partials
//      5 LN2-folded MLP1: gelu(rstd*acc - mean*rstd*c + bb) -> fp16
// ---------------------------------------------------------------------------
#define KW    40
#define ROWB  80
#define STGB  (128 * ROWB)
#define NSTG  4
#define GSM_BIAS 0
#define GSM_A    1024
#define GSM_B    (GSM_A + NSTG * STGB)
#define GSM_TOTAL (GSM_B + NSTG * STGB)

__device__ __forceinline__ void g4_load(char* smem, const __half* A, const __half* Bt,
                                        size_t aBase, size_t bBase, int K,
                                        int st, int ko, int tid) {
    char* pa = smem + GSM_A + st * STGB;
    char* pb = smem + GSM_B + st * STGB;
#pragma unroll
    for (int j = 0; j < 4; j++) {
        int c = tid + 128 * j;
        int r = c >> 2, sg = c & 3;
        cp16(pa + r * ROWB + sg * 16, A + aBase + (size_t)r * K + ko + sg * 8);
        cp16(pb + r * ROWB + sg * 16, Bt + bBase + (size_t)r * K + ko + sg * 8);
    }
}

template <int EPI>
__global__ __launch_bounds__(128, 2) void gemm16(const __half* __restrict__ A,
                                                 const __half* __restrict__ Bt,
                                                 const float* __restrict__ bias,
                                                 const __half* __restrict__ res,
                                                 const float* __restrict__ res32,
                                                 const float* __restrict__ stats,
                                                 const float* __restrict__ cvec,
                                                 float2* __restrict__ part,
                                                 void* __restrict__ outp,
                                                 int M, int N, int K) {
    extern __shared__ char smem[];
    int tid = threadIdx.x;
    int bx = blockIdx.x, by = blockIdx.y;
    size_t aBase = (size_t)by * 128 * K;
    size_t bBase = (size_t)bx * 128 * K;

    ((float*)(smem + GSM_BIAS))[tid] = bias[bx * 128 + tid];
    if constexpr (EPI == 5)
        ((float*)(smem + GSM_BIAS))[128 + tid] = cvec[bx * 128 + tid];

    int niter = K >> 5;

#pragma unroll
    for (int st = 0; st < 3; st++) {
        g4_load(smem, A, Bt, aBase, bBase, K, st, st << 5, tid);
        cp_commit();
    }

    int warp = tid >> 5, lane = tid & 31;
    int wm = warp >> 1, wn = warp & 1;          // 2x2 warps; warp tile 64x64

    float acc[4][8][4];
#pragma unroll
    for (int mi = 0; mi < 4; mi++)
#pragma unroll
        for (int ni = 0; ni < 8; ni++)
#pragma unroll
            for (int j = 0; j < 4; j++) acc[mi][ni][j] = 0.0f;

    int aRow = wm * 64 + (lane & 7) + ((lane >> 3) & 1) * 8;
    int aCol = (lane >> 4) * 8;
    int bRow = wn * 64 + (lane & 7) + (lane >> 4) * 8;
    int bCol = ((lane >> 3) & 1) * 8;

    uint32_t fa[2][4][4];
    uint32_t fb[2][8][2];

    cp_wait1();
    __syncthreads();

    {
        const __half* sa = (const __half*)(smem + GSM_A);
        const __half* sb = (const __half*)(smem + GSM_B);
#pragma unroll
        for (int mi = 0; mi < 4; mi++)
            ldm4(fa[0][mi][0], fa[0][mi][1], fa[0][mi][2], fa[0][mi][3],
                 sa + (size_t)(aRow + mi * 16) * KW + aCol);
#pragma unroll
        for (int nj = 0; nj < 4; nj++) {
            uint32_t q0, q1, q2, q3;
            ldm4(q0, q1, q2, q3, sb + (size_t)(bRow + nj * 16) * KW + bCol);
            fb[0][nj * 2][0] = q0; fb[0][nj * 2][1] = q1;
            fb[0][nj * 2 + 1][0] = q2; fb[0][nj * 2 + 1][1] = q3;
        }
    }

    for (int it = 0; it < niter; ++it) {
        int st = it & 3;
        const __half* sa = (const __half*)(smem + GSM_A + st * STGB);
        const __half* sb = (const __half*)(smem + GSM_B + st * STGB);

#pragma unroll
        for (int mi = 0; mi < 4; mi++)
            ldm4(fa[1][mi][0], fa[1][mi][1], fa[1][mi][2], fa[1][mi][3],
                 sa + (size_t)(aRow + mi * 16) * KW + 16 + aCol);
#pragma unroll
        for (int nj = 0; nj < 4; nj++) {
            uint32_t q0, q1, q2, q3;
            ldm4(q0, q1, q2, q3, sb + (size_t)(bRow + nj * 16) * KW + 16 + bCol);
            fb[1][nj * 2][0] = q0; fb[1][nj * 2][1] = q1;
            fb[1][nj * 2 + 1][0] = q2; fb[1][nj * 2 + 1][1] = q3;
        }
#pragma unroll
        for (int mi = 0; mi < 4; mi++)
#pragma unroll
            for (int ni = 0; ni < 8; ni++)
                mma16816(acc[mi][ni][0], acc[mi][ni][1], acc[mi][ni][2], acc[mi][ni][3],
                         fa[0][mi][0], fa[0][mi][1], fa[0][mi][2], fa[0][mi][3],
                         fb[0][ni][0], fb[0][ni][1]);

        cp_wait1();
        __syncthreads();
        if (it + 3 < niter)
            g4_load(smem, A, Bt, aBase, bBase, K, (it + 3) & 3, (it + 3) << 5, tid);
        cp_commit();

        if (it + 1 < niter) {
            int sn = (it + 1) & 3;
            const __half* sa2 = (const __half*)(smem + GSM_A + sn * STGB);
            const __half* sb2 = (const __half*)(smem + GSM_B + sn * STGB);
#pragma unroll
            for (int mi = 0; mi < 4; mi++)
                ldm4(fa[0][mi][0], fa[0][mi][1], fa[0][mi][2], fa[0][mi][3],
                     sa2 + (size_t)(aRow + mi * 16) * KW + aCol);
#pragma unroll
            for (int nj = 0; nj < 4; nj++) {
                uint32_t q0, q1, q2, q3;
                ldm4(q0, q1, q2, q3, sb2 + (size_t)(bRow + nj * 16) * KW + bCol);
                fb[0][nj * 2][0] = q0; fb[0][nj * 2][1] = q1;
                fb[0][nj * 2 + 1][0] = q2; fb[0][nj * 2 + 1][1] = q3;
            }
        }
#pragma unroll
        for (int mi = 0; mi < 4; mi++)
#pragma unroll
            for (int ni = 0; ni < 8; ni++)
                mma16816(acc[mi][ni][0], acc[mi][ni][1], acc[mi][ni][2], acc[mi][ni][3],
                         fa[1][mi][0], fa[1][mi][1], fa[1][mi][2], fa[1][mi][3],
                         fb[1][ni][0], fb[1][ni][1]);
    }

    // epilogue
    const float* sbias = (const float*)(smem + GSM_BIAS);
    int gm0 = by * 128 + wm * 64;
    int gn0 = bx * 128 + wn * 64;
    int ln0 = wn * 64;

    if constexpr (EPI == 4) {
        // fused window-reverse + roll + hs residual -> x, with stat partials
        float* sred = (float*)(smem + GSM_A);      // 128 rows x 2 warps x 2 floats
        __syncthreads();                           // stage smem reads all done
#pragma unroll
        for (int mi = 0; mi < 4; mi++) {
#pragma unroll
            for (int hf = 0; hf < 2; hf++) {
                int gr = gm0 + mi * 16 + (lane >> 2) + hf * 8;
                int bimg = gr >> 12;
                int rem  = gr & 4095;
                int wid  = rem >> 6, t = rem & 63;
                int wy = wid >> 3, wx = wid & 7;
                int hr = wy * 8 + (t >> 3), wr = wx * 8 + (t & 7);
                int h0 = (hr + SHIFT) & 63, w0 = (wr + SHIFT) & 63;
                size_t nat = (size_t)(bimg << 12) + (h0 << 6) + w0;
                float s = 0.0f, s2 = 0.0f;
#pragma unroll
                for (int ni = 0; ni < 8; ni++) {
                    int col = gn0 + ni * 8 + (lane & 3) * 2;
                    int lcol = ln0 + ni * 8 + (lane & 3) * 2;
                    float v0 = acc[mi][ni][hf * 2 + 0] + sbias[lcol];
                    float v1 = acc[mi][ni][hf * 2 + 1] + sbias[lcol + 1];
                    float2 hv = *(const float2*)(res32 + nat * CDIM + col);
                    v0 += hv.x; v1 += hv.y;
                    *(__half2*)((__half*)outp + nat * CDIM + col) =
                        __floats2half2_rn(v0, v1);
                    s  += v0 + v1;
                    s2 += v0 * v0 + v1 * v1;
                }
                s  += __shfl_xor_sync(0xffffffffu, s, 1);
                s  += __shfl_xor_sync(0xffffffffu, s, 2);
                s2 += __shfl_xor_sync(0xffffffffu, s2, 1);
                s2 += __shfl_xor_sync(0xffffffffu, s2, 2);
                if ((lane & 3) == 0) {
                    int lr = wm * 64 + mi * 16 + (lane >> 2) + hf * 8;
                    sred[(lr * 2 + wn) * 2 + 0] = s;
                    sred[(lr * 2 + wn) * 2 + 1] = s2;
                }
            }
        }
        __syncthreads();
        {
            int gr = by * 128 + tid;
            int bimg = gr >> 12;
            int rem  = gr & 4095;
            int wid  = rem >> 6, t = rem & 63;
            int wy = wid >> 3, wx = wid & 7;
            int hr = wy * 8 + (t >> 3), wr = wx * 8 + (t & 7);
            int h0 = (hr + SHIFT) & 63, w0 = (wr + SHIFT) & 63;
            size_t nat = (size_t)(bimg << 12) + (h0 << 6) + w0;
            float s  = sred[(tid * 2 + 0) * 2 + 0] + sred[(tid * 2 + 1) * 2 + 0];
            float s2 = sred[(tid * 2 + 0) * 2 + 1] + sred[(tid * 2 + 1) * 2 + 1];
            part[(size_t)bx * MTOK + nat] = make_float2(s, s2);
        }
    } else if constexpr (EPI == 5) {
        const float* scv = sbias + 128;
#pragma unroll
        for (int mi = 0; mi < 4; mi++) {
#pragma unroll
            for (int hf = 0; hf < 2; hf++) {
                int gr = gm0 + mi * 16 + (lane >> 2) + hf * 8;
                float2 st2 = ((const float2*)stats)[gr];
                float rstd = st2.y;
                float mr = -st2.x * st2.y;
#pragma unroll
                for (int ni = 0; ni < 8; ni++) {
                    int col = gn0 + ni * 8 + (lane & 3) * 2;
                    int lcol = ln0 + ni * 8 + (lane & 3) * 2;
                    float v0 = fmaf(acc[mi][ni][hf * 2 + 0], rstd,
                                    fmaf(mr, scv[lcol], sbias[lcol]));
                    float v1 = fmaf(acc[mi][ni][hf * 2 + 1], rstd,
                                    fmaf(mr, scv[lcol + 1], sbias[lcol + 1]));
                    *(__half2*)((__half*)outp + (size_t)gr * N + col) =
                        __floats2half2_rn(gelu_tanh(v0), gelu_tanh(v1));
                }
            }
        }
    } else {
#pragma unroll
        for (int mi = 0; mi < 4; mi++) {
#pragma unroll
            for (int ni = 0; ni < 8; ni++) {
                int row = gm0 + mi * 16 + (lane >> 2);
                int col = gn0 + ni * 8 + (lane & 3) * 2;
                int lcol = ln0 + ni * 8 + (lane & 3) * 2;
                float bv0 = sbias[lcol], bv1 = sbias[lcol + 1];
#pragma unroll
                for (int hf = 0; hf < 2; hf++) {
                    int gr = row + hf * 8;
                    float v0 = acc[mi][ni][hf * 2 + 0] + bv0;
                    float v1 = acc[mi][ni][hf * 2 + 1] + bv1;
                    size_t off = (size_t)gr * N + col;
                    if constexpr (EPI == 0) {
                        *(__half2*)((__half*)outp + off) = __floats2half2_rn(v0, v1);
                    } else {
                        float2 r2 = __half22float2(*(const __half2*)(res + off));
                        v0 += r2.x;
                        v1 += r2.y;
                        *(float2*)((float*)outp + off) = make_float2(v0, v1);
                    }
                }
            }
        }
    }
}

// ---------------------------------------------------------------------------
// Kernel 3: HMMA attention. One WARP per (window, head); block = 4 heads.
// ---------------------------------------------------------------------------
#define ATT_SCALE 0.17677669529663687f
#define AH_HALVES 7680
#define ASM_SID   61440
#define ASM_TOTAL 61696

__global__ __launch_bounds__(128, 2) void k_attn_mma(const __half* __restrict__ qkv,
                                                     __half* __restrict__ attn) {
    extern __shared__ char asmem[];
    int w = blockIdx.x, hg = blockIdx.y;
    int tid = threadIdx.x, wi = tid >> 5, lane = tid & 31;
    int head = hg * 4 + wi;

    __half* sh = (__half*)asmem + wi * AH_HALVES;
    int* sid = (int*)(asmem + ASM_SID);

    const __half* base = qkv + (size_t)w * 64 * 1536 + head * 32;
#pragma unroll
    for (int i = 0; i < 8; i++) {
        int c = lane + 32 * i;
        int r = c >> 2, sg = c & 3;
        const __half* src = base + (size_t)r * 1536 + sg * 8;
        cp16(&sh[r * 40 + sg * 8], src);
        cp16(&sh[2560 + r * 40 + sg * 8], src + 512);
        cp16(&sh[5120 + r * 40 + sg * 8], src + 1024);
    }
    cp_commit();
    if (tid < 64) {
        int wim = w & 63;
        int wy = wim >> 3, wx = wim & 7;
        int hh = wy * 8 + (tid >> 3), ww = wx * 8 + (tid & 7);
        int rh = (hh < 56) ? 0 : ((hh < 60) ? 1 : 2);
        int rw = (ww < 56) ? 0 : ((ww < 60) ? 1 : 2);
        sid[tid] = rh * 3 + rw;
    }
    cp_wait0();
    __syncthreads();

    int aRow = (lane & 7) + ((lane >> 3) & 1) * 8;
    int aCol = (lane >> 4) * 8;
    int bRow = (lane & 7) + (lane >> 4) * 8;
    int bCol = ((lane >> 3) & 1) * 8;

    uint32_t qa[4][2][4];
#pragma unroll
    for (int mi = 0; mi < 4; mi++)
#pragma unroll
        for (int ks = 0; ks < 2; ks++)
            ldm4(qa[mi][ks][0], qa[mi][ks][1], qa[mi][ks][2], qa[mi][ks][3],
                 &sh[(mi * 16 + aRow) * 40 + ks * 16 + aCol]);

    float sc[4][8][4];
#pragma unroll
    for (int mi = 0; mi < 4; mi++)
#pragma unroll
        for (int ni = 0; ni < 8; ni++)
#pragma unroll
            for (int j = 0; j < 4; j++) sc[mi][ni][j] = 0.0f;

    const __half* Ksh = sh + 2560;
#pragma unroll
    for (int nh = 0; nh < 2; nh++) {
        uint32_t kb[4][2][2];
#pragma unroll
        for (int nj2 = 0; nj2 < 2; nj2++)
#pragma unroll
            for (int ks = 0; ks < 2; ks++) {
                uint32_t q0, q1, q2, q3;
                ldm4(q0, q1, q2, q3,
                     &Ksh[(nh * 32 + nj2 * 16 + bRow) * 40 + ks * 16 + bCol]);
                kb[nj2 * 2][ks][0] = q0;     kb[nj2 * 2][ks][1] = q1;
                kb[nj2 * 2 + 1][ks][0] = q2; kb[nj2 * 2 + 1][ks][1] = q3;
            }
#pragma unroll
        for (int mi = 0; mi < 4; mi++)
#pragma unroll
            for (int f = 0; f < 4; f++)
#pragma unroll
                for (int ks = 0; ks < 2; ks++)
                    mma16816(sc[mi][nh * 4 + f][0], sc[mi][nh * 4 + f][1],
                             sc[mi][nh * 4 + f][2], sc[mi][nh * 4 + f][3],
                             qa[mi][ks][0], qa[mi][ks][1], qa[mi][ks][2], qa[mi][ks][3],
                             kb[f][ks][0], kb[f][ks][1]);
    }

    int rsub = lane >> 2;
    int cbase = (lane & 3) * 2;
    int cid[16];
#pragma unroll
    for (int ni = 0; ni < 8; ni++) {
        cid[2 * ni]     = sid[ni * 8 + cbase];
        cid[2 * ni + 1] = sid[ni * 8 + cbase + 1];
    }

    float inv1[4], inv2[4];
    uint32_t pa[4][4][4];
#pragma unroll
    for (int mi = 0; mi < 4; mi++) {
        int rid1 = sid[mi * 16 + rsub];
        int rid2 = sid[mi * 16 + rsub + 8];
#pragma unroll
        for (int ni = 0; ni < 8; ni++) {
            sc[mi][ni][0] = (cid[2 * ni]     == rid1) ? sc[mi][ni][0] * ATT_SCALE : -10000.0f;
            sc[mi][ni][1] = (cid[2 * ni + 1] == rid1) ? sc[mi][ni][1] * ATT_SCALE : -10000.0f;
            sc[mi][ni][2] = (cid[2 * ni]     == rid2) ? sc[mi][ni][2] * ATT_SCALE : -10000.0f;
            sc[mi][ni][3] = (cid[2 * ni + 1] == rid2) ? sc[mi][ni][3] * ATT_SCALE : -10000.0f;
        }
        float m1 = -1e30f, m2 = -1e30f;
#pragma unroll
        for (int ni = 0; ni < 8; ni++) {
            m1 = fmaxf(m1, fmaxf(sc[mi][ni][0], sc[mi][ni][1]));
            m2 = fmaxf(m2, fmaxf(sc[mi][ni][2], sc[mi][ni][3]));
        }
        m1 = fmaxf(m1, __shfl_xor_sync(0xffffffffu, m1, 1));
        m1 = fmaxf(m1, __shfl_xor_sync(0xffffffffu, m1, 2));
        m2 = fmaxf(m2, __shfl_xor_sync(0xffffffffu, m2, 1));
        m2 = fmaxf(m2, __shfl_xor_sync(0xffffffffu, m2, 2));
        float s1 = 0.0f, s2 = 0.0f;
#pragma unroll
        for (int ni = 0; ni < 8; ni++) {
            float e0 = __expf(sc[mi][ni][0] - m1);
            float e1 = __expf(sc[mi][ni][1] - m1);
            float e2 = __expf(sc[mi][ni][2] - m2);
            float e3 = __expf(sc[mi][ni][3] - m2);
            sc[mi][ni][0] = e0; sc[mi][ni][1] = e1;
            sc[mi][ni][2] = e2; sc[mi][ni][3] = e3;
            s1 += e0 + e1; s2 += e2 + e3;
        }
        s1 += __shfl_xor_sync(0xffffffffu, s1, 1);
        s1 += __shfl_xor_sync(0xffffffffu, s1, 2);
        s2 += __shfl_xor_sync(0xffffffffu, s2, 1);
        s2 += __shfl_xor_sync(0xffffffffu, s2, 2);
        inv1[mi] = 1.0f / s1;
        inv2[mi] = 1.0f / s2;
#pragma unroll
        for (int kj = 0; kj < 4; kj++) {
            __half2 h0 = __floats2half2_rn(sc[mi][2 * kj][0], sc[mi][2 * kj][1]);
            __half2 h1 = __floats2half2_rn(sc[mi][2 * kj][2], sc[mi][2 * kj][3]);
            __half2 h2 = __floats2half2_rn(sc[mi][2 * kj + 1][0], sc[mi][2 * kj + 1][1]);
            __half2 h3 = __floats2half2_rn(sc[mi][2 * kj + 1][2], sc[mi][2 * kj + 1][3]);
            pa[mi][kj][0] = *(uint32_t*)&h0;
            pa[mi][kj][1] = *(uint32_t*)&h1;
            pa[mi][kj][2] = *(uint32_t*)&h2;
            pa[mi][kj][3] = *(uint32_t*)&h3;
        }
    }

    float ot[4][4][4];
#pragma unroll
    for (int mi = 0; mi < 4; mi++)
#pragma unroll
        for (int nj = 0; nj < 4; nj++)
#pragma unroll
            for (int j = 0; j < 4; j++) ot[mi][nj][j] = 0.0f;

    const __half* Vsh = sh + 5120;
#pragma unroll
    for (int kj = 0; kj < 4; kj++) {
        uint32_t vb[4][2];
#pragma unroll
        for (int g = 0; g < 2; g++) {
            uint32_t q0, q1, q2, q3;
            ldm4t(q0, q1, q2, q3,
                  &Vsh[(kj * 16 + (lane & 7) + ((lane >> 3) & 1) * 8) * 40 +
                       g * 16 + (lane >> 4) * 8]);
            vb[2 * g][0] = q0;     vb[2 * g][1] = q1;
            vb[2 * g + 1][0] = q2; vb[2 * g + 1][1] = q3;
        }
#pragma unroll
        for (int mi = 0; mi < 4; mi++)
#pragma unroll
            for (int nj = 0; nj < 4; nj++)
                mma16816(ot[mi][nj][0], ot[mi][nj][1], ot[mi][nj][2], ot[mi][nj][3],
                         pa[mi][kj][0], pa[mi][kj][1], pa[mi][kj][2], pa[mi][kj][3],
                         vb[nj][0], vb[nj][1]);
    }

#pragma unroll
    for (int mi = 0; mi < 4; mi++) {
        __half* o1 = attn + (size_t)(w * 64 + mi * 16 + rsub) * 512 + head * 32 + cbase;
        __half* o2 = o1 + (size_t)8 * 512;
#pragma unroll
        for (int nj = 0; nj < 4; nj++) {
            *(__half2*)(o1 + nj * 8) =
                __floats2half2_rn(ot[mi][nj][0] * inv1[mi], ot[mi][nj][1] * inv1[mi]);
            *(__half2*)(o2 + nj * 8) =
                __floats2half2_rn(ot[mi][nj][2] * inv2[mi], ot[mi][nj][3] * inv2[mi]);
        }
    }
}

// ---------------------------------------------------------------------------
// Host launcher (QKV GEMM at launch idx 3 so the profiler captures it)
// ---------------------------------------------------------------------------
extern "C" void kernel_launch(void* const* d_in, const int* in_sizes, int n_in,
                              void* d_out, int out_size) {
    const float* hs   = (const float*)d_in[0];
    const float* Wqkv = (const float*)d_in[1];
    const float* bqkv = (const float*)d_in[2];
    const float* Wo   = (const float*)d_in[3];
    const float* bo   = (const float*)d_in[4];
    const float* ln1g = (const float*)d_in[5];
    const float* ln1b = (const float*)d_in[6];
    const float* ln2g = (const float*)d_in[7];
    const float* ln2b = (const float*)d_in[8];
    const float* W1   = (const float*)d_in[9];
    const float* b1   = (const float*)d_in[10];
    const float* W2   = (const float*)d_in[11];
    const float* b2   = (const float*)d_in[12];

    __half *xw, *qkv, *attn, *xbuf, *ff, *wqkvT, *woT, *w1T, *w2T;
    float *stat, *cv, *bb;
    float2 *prt;
    cudaGetSymbolAddress((void**)&xw,    g_xw);
    cudaGetSymbolAddress((void**)&qkv,   g_qkv);
    cudaGetSymbolAddress((void**)&attn,  g_attn);
    cudaGetSymbolAddress((void**)&xbuf,  g_x);
    cudaGetSymbolAddress((void**)&ff,    g_ff);
    cudaGetSymbolAddress((void**)&prt,   g_part);
    cudaGetSymbolAddress((void**)&stat,  g_stat);
    cudaGetSymbolAddress((void**)&cv,    g_c);
    cudaGetSymbolAddress((void**)&bb,    g_bb);
    cudaGetSymbolAddress((void**)&wqkvT, g_wqkvT);
    cudaGetSymbolAddress((void**)&woT,   g_woT);
    cudaGetSymbolAddress((void**)&w1T,   g_w1T);
    cudaGetSymbolAddress((void**)&w2T,   g_w2T);

    cudaFuncSetAttribute(gemm16<0>, cudaFuncAttributeMaxDynamicSharedMemorySize, GSM_TOTAL);
    cudaFuncSetAttribute(gemm16<3>, cudaFuncAttributeMaxDynamicSharedMemorySize, GSM_TOTAL);
    cudaFuncSetAttribute(gemm16<4>, cudaFuncAttributeMaxDynamicSharedMemorySize, GSM_TOTAL);
    cudaFuncSetAttribute(gemm16<5>, cudaFuncAttributeMaxDynamicSharedMemorySize, GSM_TOTAL);
    cudaFuncSetAttribute(k_attn_mma, cudaFuncAttributeMaxDynamicSharedMemorySize, ASM_TOTAL);

    // 0: Wqkv transpose
    k_transpose<<<(512 * 1536 + 255) / 256, 256>>>(Wqkv, wqkvT, 512, 1536);
    // 1: LN1 + shift + partition
    k_ln1<<<MTOK, 128>>>(hs, ln1g, ln1b, xw);
    // 2: Wo transpose (filler so idx 3 = QKV GEMM)
    k_transpose<<<(512 * 512 + 255) / 256, 256>>>(Wo, woT, 512, 512);
    // 3: QKV GEMM  <-- profiled
    gemm16<0><<<dim3(1536 / 128, MTOK / 128), 128, GSM_TOTAL>>>(
        xw, wqkvT, bqkv, nullptr, nullptr, nullptr, nullptr, nullptr,
        qkv, MTOK, 1536, 512);
    // 4: attention
    k_attn_mma<<<dim3(2048, 4), 128, ASM_TOTAL>>>(qkv, attn);
    // 5: proj fused with window-reverse + roll + residual -> x fp16, + stat partials
    gemm16<4><<<dim3(512 / 128, MTOK / 128), 128, GSM_TOTAL>>>(
        attn, woT, bo, nullptr, hs, nullptr, nullptr, prt, xbuf, MTOK, 512, 512);
    // 6: W1 transpose (rows scaled by ln2_g)
    k_transpose_s<<<(512 * 2048 + 255) / 256, 256>>>(W1, ln2g, w1T, 512, 2048);
    // 7: c / bb vectors
    k_vec<<<FFDIM / 256, 256>>>(W1, ln2g, ln2b, b1, cv, bb);
    // 8: finalize stats from partials (tiny)
    k_stats_fin<<<MTOK / 256, 256>>>(prt, (float2*)stat);
    // 9: MLP1 with LN2 folded -> ff
    gemm16<5><<<dim3(2048 / 128, MTOK / 128), 128, GSM_TOTAL>>>(
        xbuf, w1T, bb, nullptr, nullptr, stat, cv, nullptr, ff, MTOK, 2048, 512);
    // 10: W2 transpose
    k_transpose<<<(2048 * 512 + 255) / 256, 256>>>(W2, w2T, 2048, 512);
    // 11: MLP2 + residual(fp16) -> d_out fp32
    gemm16<3><<<dim3(512 / 128, MTOK / 128), 128, GSM_TOTAL>>>(
        ff, w2T, b2, xbuf, nullptr, nullptr, nullptr, nullptr, d_out, MTOK, 512, 2048);
}